// round 1
// baseline (speedup 1.0000x reference)
#include <cuda_runtime.h>
#include <math.h>

// Problem constants
#define B_    2
#define S_    2048
#define C_    1536
#define HQ_   16
#define HKV_  4
#define DQK_  128
#define DV_   96
#define EPS_  1e-5f
#define CLIP_ 5.0f
#define M_    (B_*S_)          // 4096 rows

// ---------------- scratch (device globals; no allocation) ----------------
__device__ float g_h[M_ * C_];            // 25.2 MB  rms_bn1 output
__device__ float g_q[M_ * HQ_ * DQK_];    // 33.5 MB
__device__ float g_k[M_ * HKV_ * DQK_];   //  8.4 MB
__device__ float g_v[M_ * HKV_ * DV_];    //  6.3 MB
__device__ float g_y[M_ * HQ_ * DV_];     // 25.2 MB  attention output

// ---------------- stage 1: h = x * rsqrt(ms+eps) * g ----------------
__global__ void bn1_kernel(const float* __restrict__ x,
                           const float* __restrict__ g,
                           const float* __restrict__ ms) {
    int i = blockIdx.x * blockDim.x + threadIdx.x;        // float4 index
    int c4 = (i % (C_ / 4)) * 4;
    float4 xv = ((const float4*)x)[i];
    float4 gv = *(const float4*)&g[c4];
    float4 mv = *(const float4*)&ms[c4];
    float4 o;
    o.x = xv.x * rsqrtf(mv.x + EPS_) * gv.x;
    o.y = xv.y * rsqrtf(mv.y + EPS_) * gv.y;
    o.z = xv.z * rsqrtf(mv.z + EPS_) * gv.z;
    o.w = xv.w * rsqrtf(mv.w + EPS_) * gv.w;
    ((float4*)g_h)[i] = o;
}

// ---------------- generic 128x128x8 SGEMM, 8x8 microtile ----------------
// C[M,N] = A[M,K] @ B[K,N]; optional epilogue: (+bias[c]) * rsqrt(ms[c]+eps)*g[c]
__global__ __launch_bounds__(256)
void sgemm_kernel(const float* __restrict__ A, const float* __restrict__ Bm,
                  float* __restrict__ Cm, int M, int N, int K,
                  const float* __restrict__ bias,
                  const float* __restrict__ bn_g,
                  const float* __restrict__ bn_ms) {
    __shared__ float As[8][128];
    __shared__ float Bs[8][128];
    const int tid  = threadIdx.x;
    const int bm   = blockIdx.y * 128;
    const int bn   = blockIdx.x * 128;
    const int arow = tid >> 1;            // 0..127
    const int acol = (tid & 1) * 4;       // 0 or 4
    const int brow = tid >> 5;            // 0..7
    const int bcol = (tid & 31) * 4;      // 0..124
    const int ty   = tid >> 4;            // 0..15
    const int tx   = tid & 15;            // 0..15

    float acc[8][8];
    #pragma unroll
    for (int i = 0; i < 8; i++)
        #pragma unroll
        for (int j = 0; j < 8; j++) acc[i][j] = 0.f;

    const float* Aptr = A + (size_t)(bm + arow) * K + acol;
    const float* Bptr = Bm + (size_t)brow * N + bn + bcol;

    for (int k0 = 0; k0 < K; k0 += 8) {
        float4 av = *(const float4*)(Aptr + k0);
        As[acol + 0][arow] = av.x;
        As[acol + 1][arow] = av.y;
        As[acol + 2][arow] = av.z;
        As[acol + 3][arow] = av.w;
        *(float4*)&Bs[brow][bcol] = *(const float4*)(Bptr + (size_t)k0 * N);
        __syncthreads();
        #pragma unroll
        for (int kk = 0; kk < 8; kk++) {
            float4 a0 = *(float4*)&As[kk][ty * 8];
            float4 a1 = *(float4*)&As[kk][ty * 8 + 4];
            float4 b0 = *(float4*)&Bs[kk][tx * 8];
            float4 b1 = *(float4*)&Bs[kk][tx * 8 + 4];
            float a[8] = {a0.x, a0.y, a0.z, a0.w, a1.x, a1.y, a1.z, a1.w};
            float b[8] = {b0.x, b0.y, b0.z, b0.w, b1.x, b1.y, b1.z, b1.w};
            #pragma unroll
            for (int i = 0; i < 8; i++)
                #pragma unroll
                for (int j = 0; j < 8; j++)
                    acc[i][j] += a[i] * b[j];
        }
        __syncthreads();
    }

    #pragma unroll
    for (int i = 0; i < 8; i++) {
        int r = bm + ty * 8 + i;
        #pragma unroll
        for (int j = 0; j < 8; j++) {
            int c = bn + tx * 8 + j;
            float v = acc[i][j];
            if (bias) v += bias[c];
            if (bn_g) v *= rsqrtf(bn_ms[c] + EPS_) * bn_g[c];
            Cm[(size_t)r * N + c] = v;
        }
    }
}

// ---------------- per-head LayerNorm + RoPE for D=128 (q and k) ----------------
__global__ void ln_rope128_kernel(float* __restrict__ buf, int nHeads, int H,
                                  const float* __restrict__ g,
                                  const float* __restrict__ b) {
    int w    = (blockIdx.x * blockDim.x + threadIdx.x) >> 5;
    int lane = threadIdx.x & 31;
    if (w >= nHeads) return;
    int s = (w / H) % S_;                     // sequence position
    float* p = buf + (size_t)w * 128;

    float2 v0 = *(float2*)&p[2 * lane];       // elems (2*lane, 2*lane+1)  -> pair lane
    float2 v1 = *(float2*)&p[2 * lane + 64];  // elems (64+2*lane, ...)    -> pair lane+32

    float sum = v0.x + v0.y + v1.x + v1.y;
    #pragma unroll
    for (int o = 16; o > 0; o >>= 1) sum += __shfl_xor_sync(0xffffffffu, sum, o);
    float mu = sum * (1.f / 128.f);

    float d0 = v0.x - mu, d1 = v0.y - mu, d2 = v1.x - mu, d3 = v1.y - mu;
    float sq = d0 * d0 + d1 * d1 + d2 * d2 + d3 * d3;
    #pragma unroll
    for (int o = 16; o > 0; o >>= 1) sq += __shfl_xor_sync(0xffffffffu, sq, o);
    float inv = rsqrtf(sq * (1.f / 128.f) + EPS_);

    int i0 = 2 * lane, i1 = 2 * lane + 64;
    float a0 = d0 * inv * g[i0]     + b[i0];
    float a1 = d1 * inv * g[i0 + 1] + b[i0 + 1];
    float a2 = d2 * inv * g[i1]     + b[i1];
    float a3 = d3 * inv * g[i1 + 1] + b[i1 + 1];

    // RoPE: inv_freq[i] = 1/(i + exp(i*log(1985)/63)), theta = s * inv_freq
    const float kl = logf(1985.0f) / 63.0f;
    float f0 = 1.0f / ((float)lane        + expf((float)lane        * kl));
    float f1 = 1.0f / ((float)(lane + 32) + expf((float)(lane + 32) * kl));
    float c0, s0, c1, s1;
    sincosf((float)s * f0, &s0, &c0);
    sincosf((float)s * f1, &s1, &c1);

    float2 o0, o1;
    o0.x = a0 * c0 - a1 * s0;  o0.y = a1 * c0 + a0 * s0;
    o1.x = a2 * c1 - a3 * s1;  o1.y = a3 * c1 + a2 * s1;
    *(float2*)&p[2 * lane]      = o0;
    *(float2*)&p[2 * lane + 64] = o1;
}

// ---------------- per-head LayerNorm for D=96 (v) ----------------
__global__ void ln_v_kernel(float* __restrict__ buf, int nHeads,
                            const float* __restrict__ g,
                            const float* __restrict__ b) {
    int w    = (blockIdx.x * blockDim.x + threadIdx.x) >> 5;
    int lane = threadIdx.x & 31;
    if (w >= nHeads) return;
    float* p = buf + (size_t)w * 96;
    float x0 = p[lane], x1 = p[lane + 32], x2 = p[lane + 64];
    float sum = x0 + x1 + x2;
    #pragma unroll
    for (int o = 16; o > 0; o >>= 1) sum += __shfl_xor_sync(0xffffffffu, sum, o);
    float mu = sum * (1.f / 96.f);
    float d0 = x0 - mu, d1 = x1 - mu, d2 = x2 - mu;
    float sq = d0 * d0 + d1 * d1 + d2 * d2;
    #pragma unroll
    for (int o = 16; o > 0; o >>= 1) sq += __shfl_xor_sync(0xffffffffu, sq, o);
    float inv = rsqrtf(sq * (1.f / 96.f) + EPS_);
    p[lane]      = d0 * inv * g[lane]      + b[lane];
    p[lane + 32] = d1 * inv * g[lane + 32] + b[lane + 32];
    p[lane + 64] = d2 * inv * g[lane + 64] + b[lane + 64];
}

// ---------------- streaming attention ----------------
// One CTA handles (b, h, 64 query rows). Softcap bounds logits in [-5,5],
// so no online max is needed: p = exp(l), normalize by running sum at the end.
// dyn smem: Qst[128][64] | Kst[128][64] | Ps[64][68] | Vs[64][100]
#define ATT_SMEM_FLOATS (128*64 + 128*64 + 64*68 + 64*100)
#define ATT_SMEM_BYTES  (ATT_SMEM_FLOATS * 4)

__global__ __launch_bounds__(256)
void attn_kernel() {
    extern __shared__ float sm[];
    float* Qst = sm;                       // [d][qi]  stride 64
    float* Kst = sm + 128 * 64;            // [d][kj]  stride 64
    float* Ps  = sm + 2 * 128 * 64;        // [qi][kj] stride 68
    float* Vs  = Ps + 64 * 68;             // [kj][c]  stride 100

    const int qb = blockIdx.x;             // 0..31
    const int h  = blockIdx.y;             // 0..15
    const int bb = blockIdx.z;             // 0..1
    const int hk = h & (HKV_ - 1);
    const int tid = threadIdx.x;
    const int ty = tid >> 4, tx = tid & 15;

    // load + transpose Q block (conflict-free smem stores: lanes vary over row)
    #pragma unroll
    for (int it = 0; it < 8; it++) {
        int slot = it * 256 + tid;
        int row  = slot & 63;
        int d4   = (slot >> 6) * 4;
        const float* qr = g_q + ((size_t)(bb * S_ + qb * 64 + row) * HQ_ + h) * DQK_ + d4;
        float4 qv = *(const float4*)qr;
        Qst[(d4 + 0) * 64 + row] = qv.x;
        Qst[(d4 + 1) * 64 + row] = qv.y;
        Qst[(d4 + 2) * 64 + row] = qv.z;
        Qst[(d4 + 3) * 64 + row] = qv.w;
    }

    float rsum[4] = {0.f, 0.f, 0.f, 0.f};
    float o[4][6];
    #pragma unroll
    for (int i = 0; i < 4; i++)
        #pragma unroll
        for (int j = 0; j < 6; j++) o[i][j] = 0.f;

    const float scale = 0.08838834764831845f;   // 1/sqrt(128)

    for (int kb = 0; kb < S_ / 64; kb++) {
        __syncthreads();   // previous PV done before overwriting K/V/P
        // K block (transposed store, conflict-free)
        #pragma unroll
        for (int it = 0; it < 8; it++) {
            int slot = it * 256 + tid;
            int kj   = slot & 63;
            int d4   = (slot >> 6) * 4;
            const float* kr = g_k + ((size_t)(bb * S_ + kb * 64 + kj) * HKV_ + hk) * DQK_ + d4;
            float4 kv = *(const float4*)kr;
            Kst[(d4 + 0) * 64 + kj] = kv.x;
            Kst[(d4 + 1) * 64 + kj] = kv.y;
            Kst[(d4 + 2) * 64 + kj] = kv.z;
            Kst[(d4 + 3) * 64 + kj] = kv.w;
        }
        // V block (row-major, stride 100 floats = 400B, 16B-aligned)
        #pragma unroll
        for (int it = 0; it < 6; it++) {
            int slot = it * 256 + tid;
            int row  = slot / 24;
            int c4   = (slot % 24) * 4;
            const float* vr = g_v + ((size_t)(bb * S_ + kb * 64 + row) * HKV_ + hk) * DV_ + c4;
            *(float4*)&Vs[row * 100 + c4] = *(const float4*)vr;
        }
        __syncthreads();

        // scores: 64x64x128, 4x4 per thread
        float sc[4][4];
        #pragma unroll
        for (int i = 0; i < 4; i++)
            #pragma unroll
            for (int j = 0; j < 4; j++) sc[i][j] = 0.f;
        #pragma unroll 4
        for (int d = 0; d < 128; d++) {
            float4 qa = *(float4*)&Qst[d * 64 + ty * 4];
            float4 ka = *(float4*)&Kst[d * 64 + tx * 4];
            float a[4] = {qa.x, qa.y, qa.z, qa.w};
            float c[4] = {ka.x, ka.y, ka.z, ka.w};
            #pragma unroll
            for (int i = 0; i < 4; i++)
                #pragma unroll
                for (int j = 0; j < 4; j++)
                    sc[i][j] += a[i] * c[j];
        }
        // softcap + exp -> Ps, accumulate row sums
        #pragma unroll
        for (int i = 0; i < 4; i++) {
            int qi = ty * 4 + i;
            #pragma unroll
            for (int j = 0; j < 4; j++) {
                float l = sc[i][j] * scale;
                l = CLIP_ * tanhf(l * (1.0f / CLIP_));
                float pp = expf(l);
                Ps[qi * 68 + tx * 4 + j] = pp;
                rsum[i] += pp;
            }
        }
        __syncthreads();

        // PV: O[64][96] += P[64][64] @ V[64][96]; 4 rows x 6 cols per thread
        #pragma unroll 2
        for (int kj = 0; kj < 64; kj++) {
            float p0 = Ps[(ty * 4 + 0) * 68 + kj];
            float p1 = Ps[(ty * 4 + 1) * 68 + kj];
            float p2 = Ps[(ty * 4 + 2) * 68 + kj];
            float p3 = Ps[(ty * 4 + 3) * 68 + kj];
            #pragma unroll
            for (int j = 0; j < 6; j++) {
                float vv = Vs[kj * 100 + tx * 6 + j];
                o[0][j] += p0 * vv;
                o[1][j] += p1 * vv;
                o[2][j] += p2 * vv;
                o[3][j] += p3 * vv;
            }
        }
    }

    // reduce row sums across the 16 tx threads (xor<16 stays in half-warp = same ty)
    #pragma unroll
    for (int off = 1; off < 16; off <<= 1)
        #pragma unroll
        for (int i = 0; i < 4; i++)
            rsum[i] += __shfl_xor_sync(0xffffffffu, rsum[i], off);

    #pragma unroll
    for (int i = 0; i < 4; i++) {
        float inv = 1.0f / rsum[i];
        int s = qb * 64 + ty * 4 + i;
        float* yr = g_y + ((size_t)(bb * S_ + s) * HQ_ + h) * DV_ + tx * 6;
        #pragma unroll
        for (int j = 0; j < 6; j++) yr[j] = o[i][j] * inv;
    }
}

// ---------------- launch ----------------
extern "C" void kernel_launch(void* const* d_in, const int* in_sizes, int n_in,
                              void* d_out, int out_size) {
    const float* x      = (const float*)d_in[0];
    const float* bn1_g  = (const float*)d_in[1];
    const float* bn1_ms = (const float*)d_in[2];
    const float* Wq     = (const float*)d_in[3];
    const float* Wk     = (const float*)d_in[4];
    const float* Wv     = (const float*)d_in[5];
    const float* qn_g   = (const float*)d_in[6];
    const float* qn_b   = (const float*)d_in[7];
    const float* kn_g   = (const float*)d_in[8];
    const float* kn_b   = (const float*)d_in[9];
    const float* vn_g   = (const float*)d_in[10];
    const float* vn_b   = (const float*)d_in[11];
    const float* Wo     = (const float*)d_in[12];
    const float* bo     = (const float*)d_in[13];
    const float* bn2_g  = (const float*)d_in[14];
    const float* bn2_ms = (const float*)d_in[15];
    float* out = (float*)d_out;

    float *ph, *pq, *pk, *pv, *py;
    cudaGetSymbolAddress((void**)&ph, g_h);
    cudaGetSymbolAddress((void**)&pq, g_q);
    cudaGetSymbolAddress((void**)&pk, g_k);
    cudaGetSymbolAddress((void**)&pv, g_v);
    cudaGetSymbolAddress((void**)&py, g_y);

    cudaFuncSetAttribute(attn_kernel, cudaFuncAttributeMaxDynamicSharedMemorySize,
                         ATT_SMEM_BYTES);

    // 1. rms_bn1
    bn1_kernel<<<(M_ * C_ / 4) / 256, 256>>>(x, bn1_g, bn1_ms);

    // 2. QKV projections
    sgemm_kernel<<<dim3(HQ_ * DQK_ / 128, M_ / 128), 256>>>(ph, Wq, pq, M_, HQ_ * DQK_, C_, nullptr, nullptr, nullptr);
    sgemm_kernel<<<dim3(HKV_ * DQK_ / 128, M_ / 128), 256>>>(ph, Wk, pk, M_, HKV_ * DQK_, C_, nullptr, nullptr, nullptr);
    sgemm_kernel<<<dim3(HKV_ * DV_ / 128, M_ / 128), 256>>>(ph, Wv, pv, M_, HKV_ * DV_, C_, nullptr, nullptr, nullptr);

    // 3. LN (+RoPE for q,k)
    ln_rope128_kernel<<<(M_ * HQ_) / 8, 256>>>(pq, M_ * HQ_, HQ_, qn_g, qn_b);
    ln_rope128_kernel<<<(M_ * HKV_) / 8, 256>>>(pk, M_ * HKV_, HKV_, kn_g, kn_b);
    ln_v_kernel<<<(M_ * HKV_) / 8, 256>>>(pv, M_ * HKV_, vn_g, vn_b);

    // 4. attention
    attn_kernel<<<dim3(S_ / 64, HQ_, B_), 256, ATT_SMEM_BYTES>>>();

    // 5. out projection + bias + rms_bn2, straight into d_out
    sgemm_kernel<<<dim3(C_ / 128, M_ / 128), 256>>>(py, Wo, out, M_, C_, HQ_ * DV_, bo, bn2_g, bn2_ms);
}

// round 3
// speedup vs baseline: 1.6537x; 1.6537x over previous
#include <cuda_runtime.h>
#include <cuda_bf16.h>
#include <math.h>

// Problem constants
#define B_    2
#define S_    2048
#define C_    1536
#define HQ_   16
#define HKV_  4
#define DQK_  128
#define DV_   96
#define EPS_  1e-5f
#define CLIP_ 5.0f
#define M_    (B_*S_)          // 4096 rows

// ---------------- scratch (device globals; no allocation) ----------------
__device__ float g_q[M_ * HQ_ * DQK_];
__device__ float g_k[M_ * HKV_ * DQK_];
__device__ float g_v[M_ * HKV_ * DV_];
__device__ float g_y[M_ * HQ_ * DV_];

// bf16 hi/lo splits
__device__ __nv_bfloat16 g_hh[M_ * C_], g_hl[M_ * C_];
__device__ __nv_bfloat16 g_wqh[C_ * HQ_ * DQK_], g_wql[C_ * HQ_ * DQK_];
__device__ __nv_bfloat16 g_wkh[C_ * HKV_ * DQK_], g_wkl[C_ * HKV_ * DQK_];
__device__ __nv_bfloat16 g_wvh[C_ * HKV_ * DV_],  g_wvl[C_ * HKV_ * DV_];
__device__ __nv_bfloat16 g_woh[HQ_ * DV_ * C_],   g_wol[HQ_ * DV_ * C_];
__device__ __nv_bfloat16 g_yh[M_ * HQ_ * DV_],    g_yl[M_ * HQ_ * DV_];

// ==================== helpers ====================
__device__ __forceinline__ unsigned smem_u32(const void* p) {
    unsigned a;
    asm("{ .reg .u64 t; cvta.to.shared.u64 t, %1; cvt.u32.u64 %0, t; }" : "=r"(a) : "l"(p));
    return a;
}

#define LDSM4(r0, r1, r2, r3, addr) \
    asm volatile("ldmatrix.sync.aligned.m8n8.x4.shared.b16 {%0,%1,%2,%3}, [%4];" \
        : "=r"(r0), "=r"(r1), "=r"(r2), "=r"(r3) : "r"(addr))

#define MMA16816(d, a0, a1, a2, a3, b0, b1) \
    asm volatile("mma.sync.aligned.m16n8k16.row.col.f32.bf16.bf16.f32 " \
        "{%0,%1,%2,%3}, {%4,%5,%6,%7}, {%8,%9}, {%0,%1,%2,%3};" \
        : "+f"((d)[0]), "+f"((d)[1]), "+f"((d)[2]), "+f"((d)[3]) \
        : "r"(a0), "r"(a1), "r"(a2), "r"(a3), "r"(b0), "r"(b1))

#define CPASYNC16(dst, src) \
    asm volatile("cp.async.cg.shared.global [%0], [%1], 16;" :: "r"(dst), "l"(src))
#define CPASYNC_COMMIT() asm volatile("cp.async.commit_group;" ::: "memory")
#define CPASYNC_WAIT1()  asm volatile("cp.async.wait_group 1;" ::: "memory")
#define CPASYNC_WAIT0()  asm volatile("cp.async.wait_group 0;" ::: "memory")

// ==================== stage 1: bn1 + hi/lo split ====================
__global__ void bn1split_kernel(const float* __restrict__ x,
                                const float* __restrict__ g,
                                const float* __restrict__ ms,
                                __nv_bfloat16* __restrict__ hh,
                                __nv_bfloat16* __restrict__ hl) {
    int i = blockIdx.x * blockDim.x + threadIdx.x;        // float4 index
    int c4 = (i % (C_ / 4)) * 4;
    float4 xv = ((const float4*)x)[i];
    float4 gv = *(const float4*)&g[c4];
    float4 mv = *(const float4*)&ms[c4];
    float o[4];
    o[0] = xv.x * rsqrtf(mv.x + EPS_) * gv.x;
    o[1] = xv.y * rsqrtf(mv.y + EPS_) * gv.y;
    o[2] = xv.z * rsqrtf(mv.z + EPS_) * gv.z;
    o[3] = xv.w * rsqrtf(mv.w + EPS_) * gv.w;
    __nv_bfloat16 hi[4], lo[4];
    #pragma unroll
    for (int j = 0; j < 4; j++) {
        hi[j] = __float2bfloat16(o[j]);
        lo[j] = __float2bfloat16(o[j] - __bfloat162float(hi[j]));
    }
    *(__nv_bfloat162*)&hh[i * 4]     = __nv_bfloat162(hi[0], hi[1]);
    *(__nv_bfloat162*)&hh[i * 4 + 2] = __nv_bfloat162(hi[2], hi[3]);
    *(__nv_bfloat162*)&hl[i * 4]     = __nv_bfloat162(lo[0], lo[1]);
    *(__nv_bfloat162*)&hl[i * 4 + 2] = __nv_bfloat162(lo[2], lo[3]);
}

// ---------------- y hi/lo split ----------------
__global__ void ysplit_kernel(const float* __restrict__ y,
                              __nv_bfloat16* __restrict__ yh,
                              __nv_bfloat16* __restrict__ yl) {
    int i = blockIdx.x * blockDim.x + threadIdx.x;        // float4 index
    float4 v = ((const float4*)y)[i];
    float o[4] = {v.x, v.y, v.z, v.w};
    __nv_bfloat16 hi[4], lo[4];
    #pragma unroll
    for (int j = 0; j < 4; j++) {
        hi[j] = __float2bfloat16(o[j]);
        lo[j] = __float2bfloat16(o[j] - __bfloat162float(hi[j]));
    }
    *(__nv_bfloat162*)&yh[i * 4]     = __nv_bfloat162(hi[0], hi[1]);
    *(__nv_bfloat162*)&yh[i * 4 + 2] = __nv_bfloat162(hi[2], hi[3]);
    *(__nv_bfloat162*)&yl[i * 4]     = __nv_bfloat162(lo[0], lo[1]);
    *(__nv_bfloat162*)&yl[i * 4 + 2] = __nv_bfloat162(lo[2], lo[3]);
}

// ---------------- weight transpose + hi/lo split: W[K,N] -> Wt[N,K] ----------------
__global__ void transpose_split_kernel(const float* __restrict__ W,
                                       __nv_bfloat16* __restrict__ Th,
                                       __nv_bfloat16* __restrict__ Tl,
                                       int K, int N) {
    __shared__ float t[32][33];
    int n0 = blockIdx.x * 32, k0 = blockIdx.y * 32;
    int tx = threadIdx.x, ty = threadIdx.y;   // 32 x 8
    #pragma unroll
    for (int i = 0; i < 32; i += 8)
        t[ty + i][tx] = W[(size_t)(k0 + ty + i) * N + n0 + tx];
    __syncthreads();
    #pragma unroll
    for (int i = 0; i < 32; i += 8) {
        float v = t[tx][ty + i];
        __nv_bfloat16 hi = __float2bfloat16(v);
        float lo = v - __bfloat162float(hi);
        Th[(size_t)(n0 + ty + i) * K + k0 + tx] = hi;
        Tl[(size_t)(n0 + ty + i) * K + k0 + tx] = __float2bfloat16(lo);
    }
}

// ==================== mma.sync bf16 3-term GEMM ====================
// C[M,N] = Ah@Bh^T + Ah@Bl^T + Al@Bh^T; A:[M,K] K-major, Bt:[N,K] K-major.
// CTA 128x128, K-tile 64 (128B rows, SW128 swizzle), cp.async double buffer.
// 8 warps: warp tile 64x32 (wm = wid&1, wn = wid>>2... wn = wid>>1).
#define GEMM_SMEM (2 * 65536)

__global__ __launch_bounds__(256, 1)
void mma_gemm_kernel(const __nv_bfloat16* __restrict__ Ah, const __nv_bfloat16* __restrict__ Al,
                     const __nv_bfloat16* __restrict__ Bh, const __nv_bfloat16* __restrict__ Bl,
                     float* __restrict__ Cm, int Mdim, int Ndim, int Kdim,
                     const float* __restrict__ bias,
                     const float* __restrict__ bn_g,
                     const float* __restrict__ bn_ms) {
    extern __shared__ __align__(1024) char sm[];
    const unsigned sb = smem_u32(sm);
    const int tid = threadIdx.x, wid = tid >> 5, lane = tid & 31;
    const int bm = blockIdx.y * 128, bn = blockIdx.x * 128;
    const int wm = wid & 1, wn = wid >> 1;

    const __nv_bfloat16* srcs[4] = {Ah, Al, Bh, Bl};
    const int rowbase[4] = {bm, bm, bn, bn};
    const int KT = Kdim >> 6;

    auto load_tile_async = [&](int kt, int buf) {
        unsigned base = sb + buf * 65536;
        #pragma unroll
        for (int p = 0; p < 4; p++) {
            const __nv_bfloat16* src = srcs[p] + (size_t)rowbase[p] * Kdim + kt * 64;
            #pragma unroll
            for (int it = 0; it < 4; it++) {
                int chunk = it * 256 + tid;          // 0..1023
                int row = chunk >> 3, c = chunk & 7;
                unsigned off = row * 128 + c * 16;
                off ^= (off >> 3) & 0x70;
                CPASYNC16(base + p * 16384 + off, (const void*)(src + (size_t)row * Kdim + c * 8));
            }
        }
        CPASYNC_COMMIT();
    };

    float acc[4][4][4];
    #pragma unroll
    for (int a = 0; a < 4; a++)
        #pragma unroll
        for (int n = 0; n < 4; n++)
            #pragma unroll
            for (int q = 0; q < 4; q++) acc[a][n][q] = 0.f;

    // per-lane ldmatrix address components (unswizzled row / byte offsets)
    const int a_row  = wm * 64 + (lane & 15);          // + a*16
    const unsigned a_byte = (lane >> 4) << 4;          // + ks*32
    const int b_row  = wn * 32 + (lane & 7) + ((lane >> 4) << 3);  // + p*16
    const unsigned b_byte = ((lane >> 3) & 1) << 4;    // + ks*32

    load_tile_async(0, 0);

    for (int kt = 0; kt < KT; kt++) {
        int b = kt & 1;
        if (kt + 1 < KT) { load_tile_async(kt + 1, b ^ 1); CPASYNC_WAIT1(); }
        else             { CPASYNC_WAIT0(); }
        __syncthreads();

        unsigned baseA = sb + b * 65536;        // Ah
        unsigned baseAl = baseA + 16384;
        unsigned baseBh = baseA + 32768;
        unsigned baseBl = baseA + 49152;

        #pragma unroll
        for (int ks = 0; ks < 4; ks++) {
            unsigned bh[8], bl[8];
            #pragma unroll
            for (int p = 0; p < 2; p++) {
                unsigned off = (unsigned)(b_row + p * 16) * 128 + b_byte + ks * 32;
                off ^= (off >> 3) & 0x70;
                LDSM4(bh[p*4+0], bh[p*4+1], bh[p*4+2], bh[p*4+3], baseBh + off);
                LDSM4(bl[p*4+0], bl[p*4+1], bl[p*4+2], bl[p*4+3], baseBl + off);
            }
            #pragma unroll
            for (int a = 0; a < 4; a++) {
                unsigned offA = (unsigned)(a_row + a * 16) * 128 + a_byte + ks * 32;
                offA ^= (offA >> 3) & 0x70;
                unsigned ah0, ah1, ah2, ah3, al0, al1, al2, al3;
                LDSM4(ah0, ah1, ah2, ah3, baseA + offA);
                LDSM4(al0, al1, al2, al3, baseAl + offA);
                #pragma unroll
                for (int nat = 0; nat < 4; nat++) {
                    int p = nat >> 1, q = nat & 1;
                    unsigned b0 = bh[p*4 + q*2], b1 = bh[p*4 + q*2 + 1];
                    unsigned c0 = bl[p*4 + q*2], c1 = bl[p*4 + q*2 + 1];
                    MMA16816(acc[a][nat], ah0, ah1, ah2, ah3, b0, b1);
                    MMA16816(acc[a][nat], al0, al1, al2, al3, b0, b1);
                    MMA16816(acc[a][nat], ah0, ah1, ah2, ah3, c0, c1);
                }
            }
        }
        __syncthreads();
    }

    // ---- epilogue ----
    #pragma unroll
    for (int a = 0; a < 4; a++) {
        int r0 = bm + wm * 64 + a * 16 + (lane >> 2);
        #pragma unroll
        for (int nat = 0; nat < 4; nat++) {
            int c = bn + wn * 32 + nat * 8 + (lane & 3) * 2;
            float f0 = 1.f, f1 = 1.f, b0 = 0.f, b1 = 0.f;
            if (bias) { b0 = bias[c]; b1 = bias[c + 1]; }
            if (bn_g) {
                f0 = rsqrtf(bn_ms[c] + EPS_) * bn_g[c];
                f1 = rsqrtf(bn_ms[c + 1] + EPS_) * bn_g[c + 1];
            }
            float2 v0, v1;
            v0.x = (acc[a][nat][0] + b0) * f0;
            v0.y = (acc[a][nat][1] + b1) * f1;
            v1.x = (acc[a][nat][2] + b0) * f0;
            v1.y = (acc[a][nat][3] + b1) * f1;
            *(float2*)&Cm[(size_t)r0 * Ndim + c]       = v0;
            *(float2*)&Cm[(size_t)(r0 + 8) * Ndim + c] = v1;
        }
    }
}

// ---------------- per-head LayerNorm + RoPE for D=128 (q and k) ----------------
__global__ void ln_rope128_kernel(float* __restrict__ buf, int nHeads, int H,
                                  const float* __restrict__ g,
                                  const float* __restrict__ b) {
    int w    = (blockIdx.x * blockDim.x + threadIdx.x) >> 5;
    int lane = threadIdx.x & 31;
    if (w >= nHeads) return;
    int s = (w / H) % S_;
    float* p = buf + (size_t)w * 128;

    float2 v0 = *(float2*)&p[2 * lane];
    float2 v1 = *(float2*)&p[2 * lane + 64];

    float sum = v0.x + v0.y + v1.x + v1.y;
    #pragma unroll
    for (int o = 16; o > 0; o >>= 1) sum += __shfl_xor_sync(0xffffffffu, sum, o);
    float mu = sum * (1.f / 128.f);

    float d0 = v0.x - mu, d1 = v0.y - mu, d2 = v1.x - mu, d3 = v1.y - mu;
    float sq = d0 * d0 + d1 * d1 + d2 * d2 + d3 * d3;
    #pragma unroll
    for (int o = 16; o > 0; o >>= 1) sq += __shfl_xor_sync(0xffffffffu, sq, o);
    float inv = rsqrtf(sq * (1.f / 128.f) + EPS_);

    int i0 = 2 * lane, i1 = 2 * lane + 64;
    float a0 = d0 * inv * g[i0]     + b[i0];
    float a1 = d1 * inv * g[i0 + 1] + b[i0 + 1];
    float a2 = d2 * inv * g[i1]     + b[i1];
    float a3 = d3 * inv * g[i1 + 1] + b[i1 + 1];

    const float kl = logf(1985.0f) / 63.0f;
    float f0 = 1.0f / ((float)lane        + expf((float)lane        * kl));
    float f1 = 1.0f / ((float)(lane + 32) + expf((float)(lane + 32) * kl));
    float c0, s0, c1, s1;
    sincosf((float)s * f0, &s0, &c0);
    sincosf((float)s * f1, &s1, &c1);

    float2 o0, o1;
    o0.x = a0 * c0 - a1 * s0;  o0.y = a1 * c0 + a0 * s0;
    o1.x = a2 * c1 - a3 * s1;  o1.y = a3 * c1 + a2 * s1;
    *(float2*)&p[2 * lane]      = o0;
    *(float2*)&p[2 * lane + 64] = o1;
}

// ---------------- per-head LayerNorm for D=96 (v) ----------------
__global__ void ln_v_kernel(float* __restrict__ buf, int nHeads,
                            const float* __restrict__ g,
                            const float* __restrict__ b) {
    int w    = (blockIdx.x * blockDim.x + threadIdx.x) >> 5;
    int lane = threadIdx.x & 31;
    if (w >= nHeads) return;
    float* p = buf + (size_t)w * 96;
    float x0 = p[lane], x1 = p[lane + 32], x2 = p[lane + 64];
    float sum = x0 + x1 + x2;
    #pragma unroll
    for (int o = 16; o > 0; o >>= 1) sum += __shfl_xor_sync(0xffffffffu, sum, o);
    float mu = sum * (1.f / 96.f);
    float d0 = x0 - mu, d1 = x1 - mu, d2 = x2 - mu;
    float sq = d0 * d0 + d1 * d1 + d2 * d2;
    #pragma unroll
    for (int o = 16; o > 0; o >>= 1) sq += __shfl_xor_sync(0xffffffffu, sq, o);
    float inv = rsqrtf(sq * (1.f / 96.f) + EPS_);
    p[lane]      = d0 * inv * g[lane]      + b[lane];
    p[lane + 32] = d1 * inv * g[lane + 32] + b[lane + 32];
    p[lane + 64] = d2 * inv * g[lane + 64] + b[lane + 64];
}

// ---------------- streaming attention (fp32, softcap -> no online max) ----------------
#define ATT_SMEM_FLOATS (128*64 + 128*64 + 64*68 + 64*100)
#define ATT_SMEM_BYTES  (ATT_SMEM_FLOATS * 4)

__global__ __launch_bounds__(256)
void attn_kernel() {
    extern __shared__ float smf[];
    float* Qst = smf;                      // [d][qi]  stride 64
    float* Kst = smf + 128 * 64;           // [d][kj]  stride 64
    float* Ps  = smf + 2 * 128 * 64;       // [qi][kj] stride 68
    float* Vs  = Ps + 64 * 68;             // [kj][c]  stride 100

    const int qb = blockIdx.x;
    const int h  = blockIdx.y;
    const int bb = blockIdx.z;
    const int hk = h & (HKV_ - 1);
    const int tid = threadIdx.x;
    const int ty = tid >> 4, tx = tid & 15;

    #pragma unroll
    for (int it = 0; it < 8; it++) {
        int slot = it * 256 + tid;
        int row  = slot & 63;
        int d4   = (slot >> 6) * 4;
        const float* qr = g_q + ((size_t)(bb * S_ + qb * 64 + row) * HQ_ + h) * DQK_ + d4;
        float4 qv = *(const float4*)qr;
        Qst[(d4 + 0) * 64 + row] = qv.x;
        Qst[(d4 + 1) * 64 + row] = qv.y;
        Qst[(d4 + 2) * 64 + row] = qv.z;
        Qst[(d4 + 3) * 64 + row] = qv.w;
    }

    float rsum[4] = {0.f, 0.f, 0.f, 0.f};
    float o[4][6];
    #pragma unroll
    for (int i = 0; i < 4; i++)
        #pragma unroll
        for (int j = 0; j < 6; j++) o[i][j] = 0.f;

    const float scale = 0.08838834764831845f;

    for (int kb = 0; kb < S_ / 64; kb++) {
        __syncthreads();
        #pragma unroll
        for (int it = 0; it < 8; it++) {
            int slot = it * 256 + tid;
            int kj   = slot & 63;
            int d4   = (slot >> 6) * 4;
            const float* kr = g_k + ((size_t)(bb * S_ + kb * 64 + kj) * HKV_ + hk) * DQK_ + d4;
            float4 kv = *(const float4*)kr;
            Kst[(d4 + 0) * 64 + kj] = kv.x;
            Kst[(d4 + 1) * 64 + kj] = kv.y;
            Kst[(d4 + 2) * 64 + kj] = kv.z;
            Kst[(d4 + 3) * 64 + kj] = kv.w;
        }
        #pragma unroll
        for (int it = 0; it < 6; it++) {
            int slot = it * 256 + tid;
            int row  = slot / 24;
            int c4   = (slot % 24) * 4;
            const float* vr = g_v + ((size_t)(bb * S_ + kb * 64 + row) * HKV_ + hk) * DV_ + c4;
            *(float4*)&Vs[row * 100 + c4] = *(const float4*)vr;
        }
        __syncthreads();

        float sc[4][4];
        #pragma unroll
        for (int i = 0; i < 4; i++)
            #pragma unroll
            for (int j = 0; j < 4; j++) sc[i][j] = 0.f;
        #pragma unroll 4
        for (int d = 0; d < 128; d++) {
            float4 qa = *(float4*)&Qst[d * 64 + ty * 4];
            float4 ka = *(float4*)&Kst[d * 64 + tx * 4];
            float a[4] = {qa.x, qa.y, qa.z, qa.w};
            float c[4] = {ka.x, ka.y, ka.z, ka.w};
            #pragma unroll
            for (int i = 0; i < 4; i++)
                #pragma unroll
                for (int j = 0; j < 4; j++)
                    sc[i][j] += a[i] * c[j];
        }
        #pragma unroll
        for (int i = 0; i < 4; i++) {
            int qi = ty * 4 + i;
            #pragma unroll
            for (int j = 0; j < 4; j++) {
                float l = sc[i][j] * scale;
                l = CLIP_ * tanhf(l * (1.0f / CLIP_));
                float pp = expf(l);
                Ps[qi * 68 + tx * 4 + j] = pp;
                rsum[i] += pp;
            }
        }
        __syncthreads();

        #pragma unroll 2
        for (int kj = 0; kj < 64; kj++) {
            float p0 = Ps[(ty * 4 + 0) * 68 + kj];
            float p1 = Ps[(ty * 4 + 1) * 68 + kj];
            float p2 = Ps[(ty * 4 + 2) * 68 + kj];
            float p3 = Ps[(ty * 4 + 3) * 68 + kj];
            #pragma unroll
            for (int j = 0; j < 6; j++) {
                float vv = Vs[kj * 100 + tx * 6 + j];
                o[0][j] += p0 * vv;
                o[1][j] += p1 * vv;
                o[2][j] += p2 * vv;
                o[3][j] += p3 * vv;
            }
        }
    }

    #pragma unroll
    for (int off = 1; off < 16; off <<= 1)
        #pragma unroll
        for (int i = 0; i < 4; i++)
            rsum[i] += __shfl_xor_sync(0xffffffffu, rsum[i], off);

    #pragma unroll
    for (int i = 0; i < 4; i++) {
        float inv = 1.0f / rsum[i];
        int s = qb * 64 + ty * 4 + i;
        float* yr = g_y + ((size_t)(bb * S_ + s) * HQ_ + h) * DV_ + tx * 6;
        #pragma unroll
        for (int j = 0; j < 6; j++) yr[j] = o[i][j] * inv;
    }
}

// ---------------- launch ----------------
extern "C" void kernel_launch(void* const* d_in, const int* in_sizes, int n_in,
                              void* d_out, int out_size) {
    const float* x      = (const float*)d_in[0];
    const float* bn1_g  = (const float*)d_in[1];
    const float* bn1_ms = (const float*)d_in[2];
    const float* Wq     = (const float*)d_in[3];
    const float* Wk     = (const float*)d_in[4];
    const float* Wv     = (const float*)d_in[5];
    const float* qn_g   = (const float*)d_in[6];
    const float* qn_b   = (const float*)d_in[7];
    const float* kn_g   = (const float*)d_in[8];
    const float* kn_b   = (const float*)d_in[9];
    const float* vn_g   = (const float*)d_in[10];
    const float* vn_b   = (const float*)d_in[11];
    const float* Wo     = (const float*)d_in[12];
    const float* bo     = (const float*)d_in[13];
    const float* bn2_g  = (const float*)d_in[14];
    const float* bn2_ms = (const float*)d_in[15];
    float* out = (float*)d_out;

    float *pq, *pk, *pv, *py;
    __nv_bfloat16 *phh, *phl, *pwqh, *pwql, *pwkh, *pwkl, *pwvh, *pwvl, *pwoh, *pwol, *pyh, *pyl;
    cudaGetSymbolAddress((void**)&pq, g_q);
    cudaGetSymbolAddress((void**)&pk, g_k);
    cudaGetSymbolAddress((void**)&pv, g_v);
    cudaGetSymbolAddress((void**)&py, g_y);
    cudaGetSymbolAddress((void**)&phh, g_hh);
    cudaGetSymbolAddress((void**)&phl, g_hl);
    cudaGetSymbolAddress((void**)&pwqh, g_wqh);
    cudaGetSymbolAddress((void**)&pwql, g_wql);
    cudaGetSymbolAddress((void**)&pwkh, g_wkh);
    cudaGetSymbolAddress((void**)&pwkl, g_wkl);
    cudaGetSymbolAddress((void**)&pwvh, g_wvh);
    cudaGetSymbolAddress((void**)&pwvl, g_wvl);
    cudaGetSymbolAddress((void**)&pwoh, g_woh);
    cudaGetSymbolAddress((void**)&pwol, g_wol);
    cudaGetSymbolAddress((void**)&pyh, g_yh);
    cudaGetSymbolAddress((void**)&pyl, g_yl);

    cudaFuncSetAttribute(attn_kernel, cudaFuncAttributeMaxDynamicSharedMemorySize, ATT_SMEM_BYTES);
    cudaFuncSetAttribute(mma_gemm_kernel, cudaFuncAttributeMaxDynamicSharedMemorySize, GEMM_SMEM);

    // 1. rms_bn1 + split
    bn1split_kernel<<<(M_ * C_ / 4) / 256, 256>>>(x, bn1_g, bn1_ms, phh, phl);

    // 2. weight transposes + splits
    transpose_split_kernel<<<dim3((HQ_*DQK_)/32, C_/32), dim3(32,8)>>>(Wq, pwqh, pwql, C_, HQ_*DQK_);
    transpose_split_kernel<<<dim3((HKV_*DQK_)/32, C_/32), dim3(32,8)>>>(Wk, pwkh, pwkl, C_, HKV_*DQK_);
    transpose_split_kernel<<<dim3((HKV_*DV_)/32, C_/32), dim3(32,8)>>>(Wv, pwvh, pwvl, C_, HKV_*DV_);
    transpose_split_kernel<<<dim3(C_/32, (HQ_*DV_)/32), dim3(32,8)>>>(Wo, pwoh, pwol, HQ_*DV_, C_);

    // 3. QKV projections (tensor cores)
    mma_gemm_kernel<<<dim3(HQ_*DQK_/128, M_/128), 256, GEMM_SMEM>>>(phh, phl, pwqh, pwql, pq, M_, HQ_*DQK_, C_, nullptr, nullptr, nullptr);
    mma_gemm_kernel<<<dim3(HKV_*DQK_/128, M_/128), 256, GEMM_SMEM>>>(phh, phl, pwkh, pwkl, pk, M_, HKV_*DQK_, C_, nullptr, nullptr, nullptr);
    mma_gemm_kernel<<<dim3(HKV_*DV_/128, M_/128), 256, GEMM_SMEM>>>(phh, phl, pwvh, pwvl, pv, M_, HKV_*DV_, C_, nullptr, nullptr, nullptr);

    // 4. LN (+RoPE)
    ln_rope128_kernel<<<(M_ * HQ_) / 8, 256>>>(pq, M_ * HQ_, HQ_, qn_g, qn_b);
    ln_rope128_kernel<<<(M_ * HKV_) / 8, 256>>>(pk, M_ * HKV_, HKV_, kn_g, kn_b);
    ln_v_kernel<<<(M_ * HKV_) / 8, 256>>>(pv, M_ * HKV_, vn_g, vn_b);

    // 5. attention
    attn_kernel<<<dim3(S_ / 64, HQ_, B_), 256, ATT_SMEM_BYTES>>>();

    // 6. split y, out projection + bias + rms_bn2 (tensor cores) -> d_out
    ysplit_kernel<<<(M_ * HQ_ * DV_ / 4) / 256, 256>>>(py, pyh, pyl);
    mma_gemm_kernel<<<dim3(C_/128, M_/128), 256, GEMM_SMEM>>>(pyh, pyl, pwoh, pwol, out, M_, C_, HQ_*DV_, bo, bn2_g, bn2_ms);
}

// round 4
// speedup vs baseline: 3.9745x; 2.4034x over previous
#include <cuda_runtime.h>
#include <cuda_bf16.h>
#include <math.h>

// Problem constants
#define B_    2
#define S_    2048
#define C_    1536
#define HQ_   16
#define HKV_  4
#define DQK_  128
#define DV_   96
#define EPS_  1e-5f
#define CLIP_ 5.0f
#define M_    (B_*S_)          // 4096 rows

// ---------------- scratch (device globals; no allocation) ----------------
__device__ float g_q[M_ * HQ_ * DQK_];    // fp32 GEMM outputs (pre-LN)
__device__ float g_k[M_ * HKV_ * DQK_];
__device__ float g_v[M_ * HKV_ * DV_];

// bf16 hi/lo splits
__device__ __nv_bfloat16 g_hh[M_ * C_], g_hl[M_ * C_];
__device__ __nv_bfloat16 g_wqh[C_ * HQ_ * DQK_], g_wql[C_ * HQ_ * DQK_];
__device__ __nv_bfloat16 g_wkh[C_ * HKV_ * DQK_], g_wkl[C_ * HKV_ * DQK_];
__device__ __nv_bfloat16 g_wvh[C_ * HKV_ * DV_],  g_wvl[C_ * HKV_ * DV_];
__device__ __nv_bfloat16 g_woh[HQ_ * DV_ * C_],   g_wol[HQ_ * DV_ * C_];
__device__ __nv_bfloat16 g_yh[M_ * HQ_ * DV_],    g_yl[M_ * HQ_ * DV_];
// post-LN/RoPE bf16 hi/lo q,k,v
__device__ __nv_bfloat16 g_qh[M_ * HQ_ * DQK_],  g_ql[M_ * HQ_ * DQK_];
__device__ __nv_bfloat16 g_kh[M_ * HKV_ * DQK_], g_kl[M_ * HKV_ * DQK_];
__device__ __nv_bfloat16 g_vh[M_ * HKV_ * DV_],  g_vl[M_ * HKV_ * DV_];

// ==================== helpers ====================
__device__ __forceinline__ unsigned smem_u32(const void* p) {
    unsigned a;
    asm("{ .reg .u64 t; cvta.to.shared.u64 t, %1; cvt.u32.u64 %0, t; }" : "=r"(a) : "l"(p));
    return a;
}

#define LDSM4(r0, r1, r2, r3, addr) \
    asm volatile("ldmatrix.sync.aligned.m8n8.x4.shared.b16 {%0,%1,%2,%3}, [%4];" \
        : "=r"(r0), "=r"(r1), "=r"(r2), "=r"(r3) : "r"(addr))

#define LDSM4T(r0, r1, r2, r3, addr) \
    asm volatile("ldmatrix.sync.aligned.m8n8.x4.trans.shared.b16 {%0,%1,%2,%3}, [%4];" \
        : "=r"(r0), "=r"(r1), "=r"(r2), "=r"(r3) : "r"(addr))

#define MMA16816(d, a0, a1, a2, a3, b0, b1) \
    asm volatile("mma.sync.aligned.m16n8k16.row.col.f32.bf16.bf16.f32 " \
        "{%0,%1,%2,%3}, {%4,%5,%6,%7}, {%8,%9}, {%0,%1,%2,%3};" \
        : "+f"((d)[0]), "+f"((d)[1]), "+f"((d)[2]), "+f"((d)[3]) \
        : "r"(a0), "r"(a1), "r"(a2), "r"(a3), "r"(b0), "r"(b1))

#define CPASYNC16(dst, src) \
    asm volatile("cp.async.cg.shared.global [%0], [%1], 16;" :: "r"(dst), "l"(src))
#define CPASYNC_COMMIT() asm volatile("cp.async.commit_group;" ::: "memory")
#define CPASYNC_WAIT1()  asm volatile("cp.async.wait_group 1;" ::: "memory")
#define CPASYNC_WAIT0()  asm volatile("cp.async.wait_group 0;" ::: "memory")

__device__ __forceinline__ void split2pack(float p0, float p1, unsigned& hi, unsigned& lo) {
    __nv_bfloat16 h0 = __float2bfloat16(p0), h1 = __float2bfloat16(p1);
    float l0 = p0 - __bfloat162float(h0), l1 = p1 - __bfloat162float(h1);
    __nv_bfloat16 g0 = __float2bfloat16(l0), g1 = __float2bfloat16(l1);
    hi = (unsigned)__bfloat16_as_ushort(h0) | ((unsigned)__bfloat16_as_ushort(h1) << 16);
    lo = (unsigned)__bfloat16_as_ushort(g0) | ((unsigned)__bfloat16_as_ushort(g1) << 16);
}

// ==================== stage 1: bn1 + hi/lo split ====================
__global__ void bn1split_kernel(const float* __restrict__ x,
                                const float* __restrict__ g,
                                const float* __restrict__ ms,
                                __nv_bfloat16* __restrict__ hh,
                                __nv_bfloat16* __restrict__ hl) {
    int i = blockIdx.x * blockDim.x + threadIdx.x;        // float4 index
    int c4 = (i % (C_ / 4)) * 4;
    float4 xv = ((const float4*)x)[i];
    float4 gv = *(const float4*)&g[c4];
    float4 mv = *(const float4*)&ms[c4];
    float o[4];
    o[0] = xv.x * rsqrtf(mv.x + EPS_) * gv.x;
    o[1] = xv.y * rsqrtf(mv.y + EPS_) * gv.y;
    o[2] = xv.z * rsqrtf(mv.z + EPS_) * gv.z;
    o[3] = xv.w * rsqrtf(mv.w + EPS_) * gv.w;
    unsigned h01, l01, h23, l23;
    split2pack(o[0], o[1], h01, l01);
    split2pack(o[2], o[3], h23, l23);
    *(unsigned*)&hh[i * 4]     = h01;
    *(unsigned*)&hh[i * 4 + 2] = h23;
    *(unsigned*)&hl[i * 4]     = l01;
    *(unsigned*)&hl[i * 4 + 2] = l23;
}

// ---------------- weight transpose + hi/lo split: W[K,N] -> Wt[N,K] ----------------
__global__ void transpose_split_kernel(const float* __restrict__ W,
                                       __nv_bfloat16* __restrict__ Th,
                                       __nv_bfloat16* __restrict__ Tl,
                                       int K, int N) {
    __shared__ float t[32][33];
    int n0 = blockIdx.x * 32, k0 = blockIdx.y * 32;
    int tx = threadIdx.x, ty = threadIdx.y;   // 32 x 8
    #pragma unroll
    for (int i = 0; i < 32; i += 8)
        t[ty + i][tx] = W[(size_t)(k0 + ty + i) * N + n0 + tx];
    __syncthreads();
    #pragma unroll
    for (int i = 0; i < 32; i += 8) {
        float v = t[tx][ty + i];
        __nv_bfloat16 hi = __float2bfloat16(v);
        float lo = v - __bfloat162float(hi);
        Th[(size_t)(n0 + ty + i) * K + k0 + tx] = hi;
        Tl[(size_t)(n0 + ty + i) * K + k0 + tx] = __float2bfloat16(lo);
    }
}

// ==================== mma.sync bf16 3-term GEMM (verified round 3) ====================
#define GEMM_SMEM (2 * 65536)

__global__ __launch_bounds__(256, 1)
void mma_gemm_kernel(const __nv_bfloat16* __restrict__ Ah, const __nv_bfloat16* __restrict__ Al,
                     const __nv_bfloat16* __restrict__ Bh, const __nv_bfloat16* __restrict__ Bl,
                     float* __restrict__ Cm, int Mdim, int Ndim, int Kdim,
                     const float* __restrict__ bias,
                     const float* __restrict__ bn_g,
                     const float* __restrict__ bn_ms) {
    extern __shared__ __align__(1024) char sm[];
    const unsigned sb = smem_u32(sm);
    const int tid = threadIdx.x, wid = tid >> 5, lane = tid & 31;
    const int bm = blockIdx.y * 128, bn = blockIdx.x * 128;
    const int wm = wid & 1, wn = wid >> 1;

    const __nv_bfloat16* srcs[4] = {Ah, Al, Bh, Bl};
    const int rowbase[4] = {bm, bm, bn, bn};
    const int KT = Kdim >> 6;

    auto load_tile_async = [&](int kt, int buf) {
        unsigned base = sb + buf * 65536;
        #pragma unroll
        for (int p = 0; p < 4; p++) {
            const __nv_bfloat16* src = srcs[p] + (size_t)rowbase[p] * Kdim + kt * 64;
            #pragma unroll
            for (int it = 0; it < 4; it++) {
                int chunk = it * 256 + tid;          // 0..1023
                int row = chunk >> 3, c = chunk & 7;
                unsigned off = row * 128 + c * 16;
                off ^= (off >> 3) & 0x70;
                CPASYNC16(base + p * 16384 + off, (const void*)(src + (size_t)row * Kdim + c * 8));
            }
        }
        CPASYNC_COMMIT();
    };

    float acc[4][4][4];
    #pragma unroll
    for (int a = 0; a < 4; a++)
        #pragma unroll
        for (int n = 0; n < 4; n++)
            #pragma unroll
            for (int q = 0; q < 4; q++) acc[a][n][q] = 0.f;

    const int a_row  = wm * 64 + (lane & 15);
    const unsigned a_byte = (lane >> 4) << 4;
    const int b_row  = wn * 32 + (lane & 7) + ((lane >> 4) << 3);
    const unsigned b_byte = ((lane >> 3) & 1) << 4;

    load_tile_async(0, 0);

    for (int kt = 0; kt < KT; kt++) {
        int b = kt & 1;
        if (kt + 1 < KT) { load_tile_async(kt + 1, b ^ 1); CPASYNC_WAIT1(); }
        else             { CPASYNC_WAIT0(); }
        __syncthreads();

        unsigned baseA = sb + b * 65536;
        unsigned baseAl = baseA + 16384;
        unsigned baseBh = baseA + 32768;
        unsigned baseBl = baseA + 49152;

        #pragma unroll
        for (int ks = 0; ks < 4; ks++) {
            unsigned bh[8], bl[8];
            #pragma unroll
            for (int p = 0; p < 2; p++) {
                unsigned off = (unsigned)(b_row + p * 16) * 128 + b_byte + ks * 32;
                off ^= (off >> 3) & 0x70;
                LDSM4(bh[p*4+0], bh[p*4+1], bh[p*4+2], bh[p*4+3], baseBh + off);
                LDSM4(bl[p*4+0], bl[p*4+1], bl[p*4+2], bl[p*4+3], baseBl + off);
            }
            #pragma unroll
            for (int a = 0; a < 4; a++) {
                unsigned offA = (unsigned)(a_row + a * 16) * 128 + a_byte + ks * 32;
                offA ^= (offA >> 3) & 0x70;
                unsigned ah0, ah1, ah2, ah3, al0, al1, al2, al3;
                LDSM4(ah0, ah1, ah2, ah3, baseA + offA);
                LDSM4(al0, al1, al2, al3, baseAl + offA);
                #pragma unroll
                for (int nat = 0; nat < 4; nat++) {
                    int p = nat >> 1, q = nat & 1;
                    unsigned b0 = bh[p*4 + q*2], b1 = bh[p*4 + q*2 + 1];
                    unsigned c0 = bl[p*4 + q*2], c1 = bl[p*4 + q*2 + 1];
                    MMA16816(acc[a][nat], ah0, ah1, ah2, ah3, b0, b1);
                    MMA16816(acc[a][nat], al0, al1, al2, al3, b0, b1);
                    MMA16816(acc[a][nat], ah0, ah1, ah2, ah3, c0, c1);
                }
            }
        }
        __syncthreads();
    }

    #pragma unroll
    for (int a = 0; a < 4; a++) {
        int r0 = bm + wm * 64 + a * 16 + (lane >> 2);
        #pragma unroll
        for (int nat = 0; nat < 4; nat++) {
            int c = bn + wn * 32 + nat * 8 + (lane & 3) * 2;
            float f0 = 1.f, f1 = 1.f, b0 = 0.f, b1 = 0.f;
            if (bias) { b0 = bias[c]; b1 = bias[c + 1]; }
            if (bn_g) {
                f0 = rsqrtf(bn_ms[c] + EPS_) * bn_g[c];
                f1 = rsqrtf(bn_ms[c + 1] + EPS_) * bn_g[c + 1];
            }
            float2 v0, v1;
            v0.x = (acc[a][nat][0] + b0) * f0;
            v0.y = (acc[a][nat][1] + b1) * f1;
            v1.x = (acc[a][nat][2] + b0) * f0;
            v1.y = (acc[a][nat][3] + b1) * f1;
            *(float2*)&Cm[(size_t)r0 * Ndim + c]       = v0;
            *(float2*)&Cm[(size_t)(r0 + 8) * Ndim + c] = v1;
        }
    }
}

// ---------------- per-head LayerNorm + RoPE for D=128, fp32 in -> bf16 hi/lo out ----------------
__global__ void ln_rope128_kernel(const float* __restrict__ src,
                                  __nv_bfloat16* __restrict__ dh,
                                  __nv_bfloat16* __restrict__ dl,
                                  int nHeads, int H,
                                  const float* __restrict__ g,
                                  const float* __restrict__ b) {
    int w    = (blockIdx.x * blockDim.x + threadIdx.x) >> 5;
    int lane = threadIdx.x & 31;
    if (w >= nHeads) return;
    int s = (w / H) % S_;
    const float* p = src + (size_t)w * 128;

    float2 v0 = *(const float2*)&p[2 * lane];
    float2 v1 = *(const float2*)&p[2 * lane + 64];

    float sum = v0.x + v0.y + v1.x + v1.y;
    #pragma unroll
    for (int o = 16; o > 0; o >>= 1) sum += __shfl_xor_sync(0xffffffffu, sum, o);
    float mu = sum * (1.f / 128.f);

    float d0 = v0.x - mu, d1 = v0.y - mu, d2 = v1.x - mu, d3 = v1.y - mu;
    float sq = d0 * d0 + d1 * d1 + d2 * d2 + d3 * d3;
    #pragma unroll
    for (int o = 16; o > 0; o >>= 1) sq += __shfl_xor_sync(0xffffffffu, sq, o);
    float inv = rsqrtf(sq * (1.f / 128.f) + EPS_);

    int i0 = 2 * lane, i1 = 2 * lane + 64;
    float a0 = d0 * inv * g[i0]     + b[i0];
    float a1 = d1 * inv * g[i0 + 1] + b[i0 + 1];
    float a2 = d2 * inv * g[i1]     + b[i1];
    float a3 = d3 * inv * g[i1 + 1] + b[i1 + 1];

    const float kl = logf(1985.0f) / 63.0f;
    float f0 = 1.0f / ((float)lane        + expf((float)lane        * kl));
    float f1 = 1.0f / ((float)(lane + 32) + expf((float)(lane + 32) * kl));
    float c0, s0, c1, s1;
    sincosf((float)s * f0, &s0, &c0);
    sincosf((float)s * f1, &s1, &c1);

    float o0 = a0 * c0 - a1 * s0, o1 = a1 * c0 + a0 * s0;
    float o2 = a2 * c1 - a3 * s1, o3 = a3 * c1 + a2 * s1;

    unsigned h01, l01, h23, l23;
    split2pack(o0, o1, h01, l01);
    split2pack(o2, o3, h23, l23);
    *(unsigned*)&dh[(size_t)w * 128 + i0] = h01;
    *(unsigned*)&dl[(size_t)w * 128 + i0] = l01;
    *(unsigned*)&dh[(size_t)w * 128 + i1] = h23;
    *(unsigned*)&dl[(size_t)w * 128 + i1] = l23;
}

// ---------------- per-head LayerNorm for D=96 (v), fp32 -> bf16 hi/lo ----------------
__global__ void ln_v_kernel(const float* __restrict__ src,
                            __nv_bfloat16* __restrict__ dh,
                            __nv_bfloat16* __restrict__ dl,
                            int nHeads,
                            const float* __restrict__ g,
                            const float* __restrict__ b) {
    int w    = (blockIdx.x * blockDim.x + threadIdx.x) >> 5;
    int lane = threadIdx.x & 31;
    if (w >= nHeads) return;
    const float* p = src + (size_t)w * 96;
    float x0 = p[lane], x1 = p[lane + 32], x2 = p[lane + 64];
    float sum = x0 + x1 + x2;
    #pragma unroll
    for (int o = 16; o > 0; o >>= 1) sum += __shfl_xor_sync(0xffffffffu, sum, o);
    float mu = sum * (1.f / 96.f);
    float d0 = x0 - mu, d1 = x1 - mu, d2 = x2 - mu;
    float sq = d0 * d0 + d1 * d1 + d2 * d2;
    #pragma unroll
    for (int o = 16; o > 0; o >>= 1) sq += __shfl_xor_sync(0xffffffffu, sq, o);
    float inv = rsqrtf(sq * (1.f / 96.f) + EPS_);
    float y0 = d0 * inv * g[lane]      + b[lane];
    float y1 = d1 * inv * g[lane + 32] + b[lane + 32];
    float y2 = d2 * inv * g[lane + 64] + b[lane + 64];
    #pragma unroll
    for (int j = 0; j < 3; j++) {
        float v = (j == 0) ? y0 : (j == 1) ? y1 : y2;
        __nv_bfloat16 hi = __float2bfloat16(v);
        float lo = v - __bfloat162float(hi);
        dh[(size_t)w * 96 + lane + j * 32] = hi;
        dl[(size_t)w * 96 + lane + j * 32] = __float2bfloat16(lo);
    }
}

// ==================== mma.sync attention ====================
// CTA: (qb 128 rows, head, batch); 8 warps x 16 q rows; kv tiles of 64.
// Q smem: hi/lo [128][128]bf16 rows 256B, swizzle off^=(off>>4)&0x70.
// K smem per buffer: hi/lo [64][128]bf16 same swizzle.
// V smem per buffer: hi/lo [64][104] bf16 rows (208B pad), no swizzle (bank-stride 20 conflict-free).
#define Q_BYTES    32768
#define K_BYTES    16384
#define V_STRIDE   208
#define V_BYTES    (64 * V_STRIDE)      // 13312
#define KV_BUF     (2 * K_BYTES + 2 * V_BYTES)  // 59392
#define ATT_SMEM   (2 * Q_BYTES + 2 * KV_BUF)   // 184320

__global__ __launch_bounds__(256, 1)
void attn_mma_kernel() {
    extern __shared__ __align__(1024) char sm[];
    const unsigned sb = smem_u32(sm);
    const int qb = blockIdx.x;             // 0..15 (128 rows each)
    const int h  = blockIdx.y;             // 0..15
    const int bb = blockIdx.z;             // 0..1
    const int hk = h & (HKV_ - 1);
    const int tid = threadIdx.x, wid = tid >> 5, lane = tid & 31;

    // ---- issue Q loads (group together with kv tile 0) ----
    {
        const __nv_bfloat16* srcs[2];
        srcs[0] = g_qh; srcs[1] = g_ql;
        #pragma unroll
        for (int part = 0; part < 2; part++) {
            #pragma unroll
            for (int it = 0; it < 8; it++) {
                int chunk = it * 256 + tid;        // 0..2047
                int row = chunk >> 4, c = chunk & 15;
                unsigned off = row * 256 + c * 16;
                off ^= (off >> 4) & 0x70;
                const __nv_bfloat16* src = srcs[part] +
                    ((size_t)(bb * S_ + qb * 128 + row) * HQ_ + h) * DQK_ + c * 8;
                CPASYNC16(sb + part * Q_BYTES + off, (const void*)src);
            }
        }
    }

    auto load_kv = [&](int kt, int buf) {
        unsigned base = sb + 2 * Q_BYTES + buf * KV_BUF;
        int s0 = kt * 64;
        const __nv_bfloat16* ksrc[2] = {g_kh, g_kl};
        #pragma unroll
        for (int part = 0; part < 2; part++) {
            #pragma unroll
            for (int it = 0; it < 4; it++) {
                int chunk = it * 256 + tid;        // 0..1023
                int row = chunk >> 4, c = chunk & 15;
                unsigned off = row * 256 + c * 16;
                off ^= (off >> 4) & 0x70;
                const __nv_bfloat16* src = ksrc[part] +
                    ((size_t)(bb * S_ + s0 + row) * HKV_ + hk) * DQK_ + c * 8;
                CPASYNC16(base + part * K_BYTES + off, (const void*)src);
            }
        }
        const __nv_bfloat16* vsrc[2] = {g_vh, g_vl};
        #pragma unroll
        for (int part = 0; part < 2; part++) {
            #pragma unroll
            for (int it = 0; it < 3; it++) {
                int chunk = it * 256 + tid;        // 0..767
                int row = chunk / 12, c = chunk % 12;
                unsigned off = row * V_STRIDE + c * 16;
                const __nv_bfloat16* src = vsrc[part] +
                    ((size_t)(bb * S_ + s0 + row) * HKV_ + hk) * DV_ + c * 8;
                CPASYNC16(base + 2 * K_BYTES + part * V_BYTES + off, (const void*)src);
            }
        }
    };

    load_kv(0, 0);
    CPASYNC_COMMIT();   // group: Q + kv0

    float o_[12][4];
    #pragma unroll
    for (int t = 0; t < 12; t++)
        #pragma unroll
        for (int q = 0; q < 4; q++) o_[t][q] = 0.f;
    float rs0 = 0.f, rs1 = 0.f;

    const float scale = 0.08838834764831845f;   // 1/sqrt(128)
    const int a_row  = wid * 16 + (lane & 15);
    const unsigned a_byte = (lane >> 4) << 4;
    const int b_rowc = (lane & 7) + ((lane >> 4) << 3);
    const unsigned b_byte = ((lane >> 3) & 1) << 4;

    const int NT = S_ / 64;
    for (int kb = 0; kb < NT; kb++) {
        int b = kb & 1;
        __syncthreads();   // all warps done reading buffer b^1
        if (kb + 1 < NT) { load_kv(kb + 1, b ^ 1); CPASYNC_COMMIT(); CPASYNC_WAIT1(); }
        else             { CPASYNC_WAIT0(); }
        __syncthreads();

        unsigned kvbase = sb + 2 * Q_BYTES + b * KV_BUF;
        unsigned baseKh = kvbase, baseKl = kvbase + K_BYTES;
        unsigned baseVh = kvbase + 2 * K_BYTES, baseVl = baseVh + V_BYTES;

        // ---- scores: P[16 x 64] per warp, 3-term ----
        float sc[8][4];
        #pragma unroll
        for (int t = 0; t < 8; t++)
            #pragma unroll
            for (int q = 0; q < 4; q++) sc[t][q] = 0.f;

        #pragma unroll
        for (int ks = 0; ks < 8; ks++) {
            unsigned offA = (unsigned)a_row * 256 + a_byte + ks * 32;
            offA ^= (offA >> 4) & 0x70;
            unsigned qh0, qh1, qh2, qh3, ql0, ql1, ql2, ql3;
            LDSM4(qh0, qh1, qh2, qh3, sb + offA);
            LDSM4(ql0, ql1, ql2, ql3, sb + Q_BYTES + offA);
            #pragma unroll
            for (int p = 0; p < 4; p++) {
                unsigned offB = (unsigned)(p * 16 + b_rowc) * 256 + b_byte + ks * 32;
                offB ^= (offB >> 4) & 0x70;
                unsigned kh0, kh1, kh2, kh3, kl0, kl1, kl2, kl3;
                LDSM4(kh0, kh1, kh2, kh3, baseKh + offB);
                LDSM4(kl0, kl1, kl2, kl3, baseKl + offB);
                MMA16816(sc[2*p],   qh0, qh1, qh2, qh3, kh0, kh1);
                MMA16816(sc[2*p],   ql0, ql1, ql2, ql3, kh0, kh1);
                MMA16816(sc[2*p],   qh0, qh1, qh2, qh3, kl0, kl1);
                MMA16816(sc[2*p+1], qh0, qh1, qh2, qh3, kh2, kh3);
                MMA16816(sc[2*p+1], ql0, ql1, ql2, ql3, kh2, kh3);
                MMA16816(sc[2*p+1], qh0, qh1, qh2, qh3, kl2, kl3);
            }
        }

        // ---- softcap + exp ----
        #pragma unroll
        for (int t = 0; t < 8; t++) {
            #pragma unroll
            for (int q = 0; q < 4; q++) {
                float l = sc[t][q] * scale;
                float e = __expf(0.4f * l);                 // e^{2x}, x=l/5
                float th = 1.f - __fdividef(2.f, e + 1.f);  // tanh(x)
                float pp = __expf(CLIP_ * th);
                sc[t][q] = pp;
                if (q < 2) rs0 += pp; else rs1 += pp;
            }
        }

        // ---- P -> bf16 hi/lo A-fragments ----
        unsigned ah[4][4], al[4][4];
        #pragma unroll
        for (int j = 0; j < 4; j++) {
            split2pack(sc[2*j][0],   sc[2*j][1],   ah[j][0], al[j][0]);
            split2pack(sc[2*j][2],   sc[2*j][3],   ah[j][1], al[j][1]);
            split2pack(sc[2*j+1][0], sc[2*j+1][1], ah[j][2], al[j][2]);
            split2pack(sc[2*j+1][2], sc[2*j+1][3], ah[j][3], al[j][3]);
        }

        // ---- PV: O[16 x 96] += P @ V, 3-term ----
        unsigned voff = (unsigned)(lane & 15) * V_STRIDE + ((lane >> 4) << 4);
        #pragma unroll
        for (int ct = 0; ct < 3; ct++) {            // c in chunks of 32 (2 ldsm c-halves)
            #pragma unroll
            for (int j = 0; j < 4; j++) {
                unsigned a0 = voff + j * (16 * V_STRIDE) + ct * 64;   // ct*32 elems = 64B
                unsigned vh0, vh1, vh2, vh3, vl0, vl1, vl2, vl3;
                LDSM4T(vh0, vh1, vh2, vh3, baseVh + a0);
                LDSM4T(vl0, vl1, vl2, vl3, baseVl + a0);
                int nt = ct * 4;
                MMA16816(o_[nt],   ah[j][0], ah[j][1], ah[j][2], ah[j][3], vh0, vh1);
                MMA16816(o_[nt],   al[j][0], al[j][1], al[j][2], al[j][3], vh0, vh1);
                MMA16816(o_[nt],   ah[j][0], ah[j][1], ah[j][2], ah[j][3], vl0, vl1);
                MMA16816(o_[nt+1], ah[j][0], ah[j][1], ah[j][2], ah[j][3], vh2, vh3);
                MMA16816(o_[nt+1], al[j][0], al[j][1], al[j][2], al[j][3], vh2, vh3);
                MMA16816(o_[nt+1], ah[j][0], ah[j][1], ah[j][2], ah[j][3], vl2, vl3);
            }
            // second 16-wide c tile of this 32 chunk
            #pragma unroll
            for (int j = 0; j < 4; j++) {
                unsigned a0 = voff + j * (16 * V_STRIDE) + ct * 64 + 32;
                unsigned vh0, vh1, vh2, vh3, vl0, vl1, vl2, vl3;
                LDSM4T(vh0, vh1, vh2, vh3, baseVh + a0);
                LDSM4T(vl0, vl1, vl2, vl3, baseVl + a0);
                int nt = ct * 4 + 2;
                MMA16816(o_[nt],   ah[j][0], ah[j][1], ah[j][2], ah[j][3], vh0, vh1);
                MMA16816(o_[nt],   al[j][0], al[j][1], al[j][2], al[j][3], vh0, vh1);
                MMA16816(o_[nt],   ah[j][0], ah[j][1], ah[j][2], ah[j][3], vl0, vl1);
                MMA16816(o_[nt+1], ah[j][0], ah[j][1], ah[j][2], ah[j][3], vh2, vh3);
                MMA16816(o_[nt+1], al[j][0], al[j][1], al[j][2], al[j][3], vh2, vh3);
                MMA16816(o_[nt+1], ah[j][0], ah[j][1], ah[j][2], ah[j][3], vl2, vl3);
            }
        }
    }

    // ---- normalize + write bf16 hi/lo y ----
    rs0 += __shfl_xor_sync(0xffffffffu, rs0, 1);
    rs0 += __shfl_xor_sync(0xffffffffu, rs0, 2);
    rs1 += __shfl_xor_sync(0xffffffffu, rs1, 1);
    rs1 += __shfl_xor_sync(0xffffffffu, rs1, 2);
    float inv0 = 1.f / rs0, inv1 = 1.f / rs1;

    int r0 = qb * 128 + wid * 16 + (lane >> 2);
    size_t rowbase0 = ((size_t)(bb * S_ + r0)) * (HQ_ * DV_) + h * DV_;
    size_t rowbase1 = rowbase0 + 8 * (size_t)(HQ_ * DV_);
    #pragma unroll
    for (int nt = 0; nt < 12; nt++) {
        int c = nt * 8 + (lane & 3) * 2;
        unsigned h01, l01, h23, l23;
        split2pack(o_[nt][0] * inv0, o_[nt][1] * inv0, h01, l01);
        split2pack(o_[nt][2] * inv1, o_[nt][3] * inv1, h23, l23);
        *(unsigned*)&g_yh[rowbase0 + c] = h01;
        *(unsigned*)&g_yl[rowbase0 + c] = l01;
        *(unsigned*)&g_yh[rowbase1 + c] = h23;
        *(unsigned*)&g_yl[rowbase1 + c] = l23;
    }
}

// ---------------- launch ----------------
extern "C" void kernel_launch(void* const* d_in, const int* in_sizes, int n_in,
                              void* d_out, int out_size) {
    const float* x      = (const float*)d_in[0];
    const float* bn1_g  = (const float*)d_in[1];
    const float* bn1_ms = (const float*)d_in[2];
    const float* Wq     = (const float*)d_in[3];
    const float* Wk     = (const float*)d_in[4];
    const float* Wv     = (const float*)d_in[5];
    const float* qn_g   = (const float*)d_in[6];
    const float* qn_b   = (const float*)d_in[7];
    const float* kn_g   = (const float*)d_in[8];
    const float* kn_b   = (const float*)d_in[9];
    const float* vn_g   = (const float*)d_in[10];
    const float* vn_b   = (const float*)d_in[11];
    const float* Wo     = (const float*)d_in[12];
    const float* bo     = (const float*)d_in[13];
    const float* bn2_g  = (const float*)d_in[14];
    const float* bn2_ms = (const float*)d_in[15];
    float* out = (float*)d_out;

    float *pq, *pk, *pv;
    __nv_bfloat16 *phh, *phl, *pwqh, *pwql, *pwkh, *pwkl, *pwvh, *pwvl, *pwoh, *pwol, *pyh, *pyl;
    __nv_bfloat16 *pqh, *pql, *pkh, *pkl, *pvh, *pvl;
    cudaGetSymbolAddress((void**)&pq, g_q);
    cudaGetSymbolAddress((void**)&pk, g_k);
    cudaGetSymbolAddress((void**)&pv, g_v);
    cudaGetSymbolAddress((void**)&phh, g_hh);
    cudaGetSymbolAddress((void**)&phl, g_hl);
    cudaGetSymbolAddress((void**)&pwqh, g_wqh);
    cudaGetSymbolAddress((void**)&pwql, g_wql);
    cudaGetSymbolAddress((void**)&pwkh, g_wkh);
    cudaGetSymbolAddress((void**)&pwkl, g_wkl);
    cudaGetSymbolAddress((void**)&pwvh, g_wvh);
    cudaGetSymbolAddress((void**)&pwvl, g_wvl);
    cudaGetSymbolAddress((void**)&pwoh, g_woh);
    cudaGetSymbolAddress((void**)&pwol, g_wol);
    cudaGetSymbolAddress((void**)&pyh, g_yh);
    cudaGetSymbolAddress((void**)&pyl, g_yl);
    cudaGetSymbolAddress((void**)&pqh, g_qh);
    cudaGetSymbolAddress((void**)&pql, g_ql);
    cudaGetSymbolAddress((void**)&pkh, g_kh);
    cudaGetSymbolAddress((void**)&pkl, g_kl);
    cudaGetSymbolAddress((void**)&pvh, g_vh);
    cudaGetSymbolAddress((void**)&pvl, g_vl);

    cudaFuncSetAttribute(mma_gemm_kernel, cudaFuncAttributeMaxDynamicSharedMemorySize, GEMM_SMEM);
    cudaFuncSetAttribute(attn_mma_kernel, cudaFuncAttributeMaxDynamicSharedMemorySize, ATT_SMEM);

    // 1. rms_bn1 + split
    bn1split_kernel<<<(M_ * C_ / 4) / 256, 256>>>(x, bn1_g, bn1_ms, phh, phl);

    // 2. weight transposes + splits
    transpose_split_kernel<<<dim3((HQ_*DQK_)/32, C_/32), dim3(32,8)>>>(Wq, pwqh, pwql, C_, HQ_*DQK_);
    transpose_split_kernel<<<dim3((HKV_*DQK_)/32, C_/32), dim3(32,8)>>>(Wk, pwkh, pwkl, C_, HKV_*DQK_);
    transpose_split_kernel<<<dim3((HKV_*DV_)/32, C_/32), dim3(32,8)>>>(Wv, pwvh, pwvl, C_, HKV_*DV_);
    transpose_split_kernel<<<dim3(C_/32, (HQ_*DV_)/32), dim3(32,8)>>>(Wo, pwoh, pwol, HQ_*DV_, C_);

    // 3. QKV projections (tensor cores, fp32 out)
    mma_gemm_kernel<<<dim3(HQ_*DQK_/128, M_/128), 256, GEMM_SMEM>>>(phh, phl, pwqh, pwql, pq, M_, HQ_*DQK_, C_, nullptr, nullptr, nullptr);
    mma_gemm_kernel<<<dim3(HKV_*DQK_/128, M_/128), 256, GEMM_SMEM>>>(phh, phl, pwkh, pwkl, pk, M_, HKV_*DQK_, C_, nullptr, nullptr, nullptr);
    mma_gemm_kernel<<<dim3(HKV_*DV_/128, M_/128), 256, GEMM_SMEM>>>(phh, phl, pwvh, pwvl, pv, M_, HKV_*DV_, C_, nullptr, nullptr, nullptr);

    // 4. LN (+RoPE), fp32 -> bf16 hi/lo
    ln_rope128_kernel<<<(M_ * HQ_) / 8, 256>>>(pq, pqh, pql, M_ * HQ_, HQ_, qn_g, qn_b);
    ln_rope128_kernel<<<(M_ * HKV_) / 8, 256>>>(pk, pkh, pkl, M_ * HKV_, HKV_, kn_g, kn_b);
    ln_v_kernel<<<(M_ * HKV_) / 8, 256>>>(pv, pvh, pvl, M_ * HKV_, vn_g, vn_b);

    // 5. attention (tensor cores), writes yh/yl bf16 directly
    attn_mma_kernel<<<dim3(S_ / 128, HQ_, B_), 256, ATT_SMEM>>>();

    // 6. out projection + bias + rms_bn2 (tensor cores) -> d_out
    mma_gemm_kernel<<<dim3(C_/128, M_/128), 256, GEMM_SMEM>>>(pyh, pyl, pwoh, pwol, out, M_, C_, HQ_*DV_, bo, bn2_g, bn2_ms);
}

// round 5
// speedup vs baseline: 4.1899x; 1.0542x over previous
#include <cuda_runtime.h>
#include <cuda_bf16.h>
#include <math.h>

// Problem constants
#define B_    2
#define S_    2048
#define C_    1536
#define HQ_   16
#define HKV_  4
#define DQK_  128
#define DV_   96
#define EPS_  1e-5f
#define CLIP_ 5.0f
#define M_    (B_*S_)          // 4096 rows
#define NQKV  2944             // 2048 q + 512 k + 384 v packed columns

// ---------------- scratch (device globals; no allocation) ----------------
__device__ float g_qkv[M_ * NQKV];        // packed fp32 QKV GEMM output

// bf16 hi/lo splits
__device__ __nv_bfloat16 g_hh[M_ * C_], g_hl[M_ * C_];
__device__ __nv_bfloat16 g_wth[NQKV * C_], g_wtl[NQKV * C_];   // packed Wq|Wk|Wv transposed
__device__ __nv_bfloat16 g_woh[C_ * C_],   g_wol[C_ * C_];     // Wo transposed (1536x1536)
__device__ __nv_bfloat16 g_yh[M_ * HQ_ * DV_],    g_yl[M_ * HQ_ * DV_];
// post-LN/RoPE bf16 hi/lo q,k,v
__device__ __nv_bfloat16 g_qh[M_ * HQ_ * DQK_],  g_ql[M_ * HQ_ * DQK_];
__device__ __nv_bfloat16 g_kh[M_ * HKV_ * DQK_], g_kl[M_ * HKV_ * DQK_];
__device__ __nv_bfloat16 g_vh[M_ * HKV_ * DV_],  g_vl[M_ * HKV_ * DV_];

// ==================== helpers ====================
__device__ __forceinline__ unsigned smem_u32(const void* p) {
    unsigned a;
    asm("{ .reg .u64 t; cvta.to.shared.u64 t, %1; cvt.u32.u64 %0, t; }" : "=r"(a) : "l"(p));
    return a;
}

#define LDSM4(r0, r1, r2, r3, addr) \
    asm volatile("ldmatrix.sync.aligned.m8n8.x4.shared.b16 {%0,%1,%2,%3}, [%4];" \
        : "=r"(r0), "=r"(r1), "=r"(r2), "=r"(r3) : "r"(addr))

#define LDSM4T(r0, r1, r2, r3, addr) \
    asm volatile("ldmatrix.sync.aligned.m8n8.x4.trans.shared.b16 {%0,%1,%2,%3}, [%4];" \
        : "=r"(r0), "=r"(r1), "=r"(r2), "=r"(r3) : "r"(addr))

#define MMA16816(d, a0, a1, a2, a3, b0, b1) \
    asm volatile("mma.sync.aligned.m16n8k16.row.col.f32.bf16.bf16.f32 " \
        "{%0,%1,%2,%3}, {%4,%5,%6,%7}, {%8,%9}, {%0,%1,%2,%3};" \
        : "+f"((d)[0]), "+f"((d)[1]), "+f"((d)[2]), "+f"((d)[3]) \
        : "r"(a0), "r"(a1), "r"(a2), "r"(a3), "r"(b0), "r"(b1))

#define CPASYNC16(dst, src) \
    asm volatile("cp.async.cg.shared.global [%0], [%1], 16;" :: "r"(dst), "l"(src))
#define CPASYNC_COMMIT() asm volatile("cp.async.commit_group;" ::: "memory")
#define CPASYNC_WAIT1()  asm volatile("cp.async.wait_group 1;" ::: "memory")
#define CPASYNC_WAIT0()  asm volatile("cp.async.wait_group 0;" ::: "memory")

__device__ __forceinline__ void split2pack(float p0, float p1, unsigned& hi, unsigned& lo) {
    __nv_bfloat16 h0 = __float2bfloat16(p0), h1 = __float2bfloat16(p1);
    float l0 = p0 - __bfloat162float(h0), l1 = p1 - __bfloat162float(h1);
    __nv_bfloat16 g0 = __float2bfloat16(l0), g1 = __float2bfloat16(l1);
    hi = (unsigned)__bfloat16_as_ushort(h0) | ((unsigned)__bfloat16_as_ushort(h1) << 16);
    lo = (unsigned)__bfloat16_as_ushort(g0) | ((unsigned)__bfloat16_as_ushort(g1) << 16);
}

// ==================== stage 1: bn1 + hi/lo split ====================
__global__ void bn1split_kernel(const float* __restrict__ x,
                                const float* __restrict__ g,
                                const float* __restrict__ ms,
                                __nv_bfloat16* __restrict__ hh,
                                __nv_bfloat16* __restrict__ hl) {
    int i = blockIdx.x * blockDim.x + threadIdx.x;        // float4 index
    int c4 = (i % (C_ / 4)) * 4;
    float4 xv = ((const float4*)x)[i];
    float4 gv = *(const float4*)&g[c4];
    float4 mv = *(const float4*)&ms[c4];
    float o[4];
    o[0] = xv.x * rsqrtf(mv.x + EPS_) * gv.x;
    o[1] = xv.y * rsqrtf(mv.y + EPS_) * gv.y;
    o[2] = xv.z * rsqrtf(mv.z + EPS_) * gv.z;
    o[3] = xv.w * rsqrtf(mv.w + EPS_) * gv.w;
    unsigned h01, l01, h23, l23;
    split2pack(o[0], o[1], h01, l01);
    split2pack(o[2], o[3], h23, l23);
    *(unsigned*)&hh[i * 4]     = h01;
    *(unsigned*)&hh[i * 4 + 2] = h23;
    *(unsigned*)&hl[i * 4]     = l01;
    *(unsigned*)&hl[i * 4 + 2] = l23;
}

// ---------------- weight transpose + hi/lo split: W[K,N] -> Wt[N,K] ----------------
__global__ void transpose_split_kernel(const float* __restrict__ W,
                                       __nv_bfloat16* __restrict__ Th,
                                       __nv_bfloat16* __restrict__ Tl,
                                       int K, int N) {
    __shared__ float t[32][33];
    int n0 = blockIdx.x * 32, k0 = blockIdx.y * 32;
    int tx = threadIdx.x, ty = threadIdx.y;   // 32 x 8
    #pragma unroll
    for (int i = 0; i < 32; i += 8)
        t[ty + i][tx] = W[(size_t)(k0 + ty + i) * N + n0 + tx];
    __syncthreads();
    #pragma unroll
    for (int i = 0; i < 32; i += 8) {
        float v = t[tx][ty + i];
        __nv_bfloat16 hi = __float2bfloat16(v);
        float lo = v - __bfloat162float(hi);
        Th[(size_t)(n0 + ty + i) * K + k0 + tx] = hi;
        Tl[(size_t)(n0 + ty + i) * K + k0 + tx] = __float2bfloat16(lo);
    }
}

// ---------------- packed QKV weight transpose: Wq|Wk|Wv -> [2944][1536] hi/lo ----------------
__global__ void transpose_qkv_kernel(const float* __restrict__ Wq,
                                     const float* __restrict__ Wk,
                                     const float* __restrict__ Wv,
                                     __nv_bfloat16* __restrict__ Th,
                                     __nv_bfloat16* __restrict__ Tl) {
    __shared__ float t[32][33];
    int n0 = blockIdx.x * 32, k0 = blockIdx.y * 32;
    int tx = threadIdx.x, ty = threadIdx.y;   // 32 x 8
    const float* W; int N; int nloc;
    if (n0 < HQ_ * DQK_)                  { W = Wq; N = HQ_ * DQK_;  nloc = n0; }
    else if (n0 < HQ_ * DQK_ + HKV_ * DQK_) { W = Wk; N = HKV_ * DQK_; nloc = n0 - HQ_ * DQK_; }
    else                                   { W = Wv; N = HKV_ * DV_;  nloc = n0 - HQ_ * DQK_ - HKV_ * DQK_; }
    #pragma unroll
    for (int i = 0; i < 32; i += 8)
        t[ty + i][tx] = W[(size_t)(k0 + ty + i) * N + nloc + tx];
    __syncthreads();
    #pragma unroll
    for (int i = 0; i < 32; i += 8) {
        float v = t[tx][ty + i];
        __nv_bfloat16 hi = __float2bfloat16(v);
        float lo = v - __bfloat162float(hi);
        Th[(size_t)(n0 + ty + i) * C_ + k0 + tx] = hi;
        Tl[(size_t)(n0 + ty + i) * C_ + k0 + tx] = __float2bfloat16(lo);
    }
}

// ==================== mma.sync bf16 3-term GEMM, 3-stage pipeline ====================
#define GEMM_SMEM (3 * 65536)

__global__ __launch_bounds__(256, 1)
void mma_gemm_kernel(const __nv_bfloat16* __restrict__ Ah, const __nv_bfloat16* __restrict__ Al,
                     const __nv_bfloat16* __restrict__ Bh, const __nv_bfloat16* __restrict__ Bl,
                     float* __restrict__ Cm, int Mdim, int Ndim, int Kdim,
                     const float* __restrict__ bias,
                     const float* __restrict__ bn_g,
                     const float* __restrict__ bn_ms) {
    extern __shared__ __align__(1024) char sm[];
    const unsigned sb = smem_u32(sm);
    const int tid = threadIdx.x, wid = tid >> 5, lane = tid & 31;
    const int bm = blockIdx.y * 128, bn = blockIdx.x * 128;
    const int wm = wid & 1, wn = wid >> 1;

    const __nv_bfloat16* srcs[4] = {Ah, Al, Bh, Bl};
    const int rowbase[4] = {bm, bm, bn, bn};
    const int KT = Kdim >> 6;

    auto load_tile_async = [&](int kt, int buf) {
        unsigned base = sb + buf * 65536;
        #pragma unroll
        for (int p = 0; p < 4; p++) {
            const __nv_bfloat16* src = srcs[p] + (size_t)rowbase[p] * Kdim + kt * 64;
            #pragma unroll
            for (int it = 0; it < 4; it++) {
                int chunk = it * 256 + tid;          // 0..1023
                int row = chunk >> 3, c = chunk & 7;
                unsigned off = row * 128 + c * 16;
                off ^= (off >> 3) & 0x70;
                CPASYNC16(base + p * 16384 + off, (const void*)(src + (size_t)row * Kdim + c * 8));
            }
        }
        CPASYNC_COMMIT();
    };

    float acc[4][4][4];
    #pragma unroll
    for (int a = 0; a < 4; a++)
        #pragma unroll
        for (int n = 0; n < 4; n++)
            #pragma unroll
            for (int q = 0; q < 4; q++) acc[a][n][q] = 0.f;

    const int a_row  = wm * 64 + (lane & 15);
    const unsigned a_byte = (lane >> 4) << 4;
    const int b_row  = wn * 32 + (lane & 7) + ((lane >> 4) << 3);
    const unsigned b_byte = ((lane >> 3) & 1) << 4;

    load_tile_async(0, 0);
    load_tile_async(1, 1);

    for (int kt = 0; kt < KT; kt++) {
        int b = kt % 3;
        if (kt + 1 < KT) CPASYNC_WAIT1(); else CPASYNC_WAIT0();
        __syncthreads();
        if (kt + 2 < KT) load_tile_async(kt + 2, (kt + 2) % 3);

        unsigned baseA = sb + b * 65536;
        unsigned baseAl = baseA + 16384;
        unsigned baseBh = baseA + 32768;
        unsigned baseBl = baseA + 49152;

        #pragma unroll
        for (int ks = 0; ks < 4; ks++) {
            unsigned bh[8], bl[8];
            #pragma unroll
            for (int p = 0; p < 2; p++) {
                unsigned off = (unsigned)(b_row + p * 16) * 128 + b_byte + ks * 32;
                off ^= (off >> 3) & 0x70;
                LDSM4(bh[p*4+0], bh[p*4+1], bh[p*4+2], bh[p*4+3], baseBh + off);
                LDSM4(bl[p*4+0], bl[p*4+1], bl[p*4+2], bl[p*4+3], baseBl + off);
            }
            #pragma unroll
            for (int a = 0; a < 4; a++) {
                unsigned offA = (unsigned)(a_row + a * 16) * 128 + a_byte + ks * 32;
                offA ^= (offA >> 3) & 0x70;
                unsigned ah0, ah1, ah2, ah3, al0, al1, al2, al3;
                LDSM4(ah0, ah1, ah2, ah3, baseA + offA);
                LDSM4(al0, al1, al2, al3, baseAl + offA);
                #pragma unroll
                for (int nat = 0; nat < 4; nat++) {
                    int p = nat >> 1, q = nat & 1;
                    unsigned b0 = bh[p*4 + q*2], b1 = bh[p*4 + q*2 + 1];
                    unsigned c0 = bl[p*4 + q*2], c1 = bl[p*4 + q*2 + 1];
                    MMA16816(acc[a][nat], ah0, ah1, ah2, ah3, b0, b1);
                    MMA16816(acc[a][nat], al0, al1, al2, al3, b0, b1);
                    MMA16816(acc[a][nat], ah0, ah1, ah2, ah3, c0, c1);
                }
            }
        }
    }

    #pragma unroll
    for (int a = 0; a < 4; a++) {
        int r0 = bm + wm * 64 + a * 16 + (lane >> 2);
        #pragma unroll
        for (int nat = 0; nat < 4; nat++) {
            int c = bn + wn * 32 + nat * 8 + (lane & 3) * 2;
            float f0 = 1.f, f1 = 1.f, b0 = 0.f, b1 = 0.f;
            if (bias) { b0 = bias[c]; b1 = bias[c + 1]; }
            if (bn_g) {
                f0 = rsqrtf(bn_ms[c] + EPS_) * bn_g[c];
                f1 = rsqrtf(bn_ms[c + 1] + EPS_) * bn_g[c + 1];
            }
            float2 v0, v1;
            v0.x = (acc[a][nat][0] + b0) * f0;
            v0.y = (acc[a][nat][1] + b1) * f1;
            v1.x = (acc[a][nat][2] + b0) * f0;
            v1.y = (acc[a][nat][3] + b1) * f1;
            *(float2*)&Cm[(size_t)r0 * Ndim + c]       = v0;
            *(float2*)&Cm[(size_t)(r0 + 8) * Ndim + c] = v1;
        }
    }
}

// ---------------- merged LN (+RoPE) over packed QKV, fp32 -> bf16 hi/lo ----------------
// warp slots per row: 0-15 q (rope), 16-19 k (rope), 20-23 v (no rope, D=96)
__global__ void ln_all_kernel(const float* __restrict__ qkv,
                              const float* __restrict__ qn_g, const float* __restrict__ qn_b,
                              const float* __restrict__ kn_g, const float* __restrict__ kn_b,
                              const float* __restrict__ vn_g, const float* __restrict__ vn_b) {
    int w    = (blockIdx.x * blockDim.x + threadIdx.x) >> 5;
    int lane = threadIdx.x & 31;
    int row  = w / 24, slot = w - row * 24;
    if (row >= M_) return;
    int s = row & (S_ - 1);

    if (slot < 20) {
        const float* p; const float *g, *b;
        __nv_bfloat16 *dh, *dl; size_t dst;
        if (slot < 16) {
            p = qkv + (size_t)row * NQKV + slot * 128;
            g = qn_g; b = qn_b; dh = g_qh; dl = g_ql;
            dst = ((size_t)row * HQ_ + slot) * 128;
        } else {
            p = qkv + (size_t)row * NQKV + 2048 + (slot - 16) * 128;
            g = kn_g; b = kn_b; dh = g_kh; dl = g_kl;
            dst = ((size_t)row * HKV_ + (slot - 16)) * 128;
        }
        float2 v0 = *(const float2*)&p[2 * lane];
        float2 v1 = *(const float2*)&p[2 * lane + 64];

        float sum = v0.x + v0.y + v1.x + v1.y;
        #pragma unroll
        for (int o = 16; o > 0; o >>= 1) sum += __shfl_xor_sync(0xffffffffu, sum, o);
        float mu = sum * (1.f / 128.f);

        float d0 = v0.x - mu, d1 = v0.y - mu, d2 = v1.x - mu, d3 = v1.y - mu;
        float sq = d0 * d0 + d1 * d1 + d2 * d2 + d3 * d3;
        #pragma unroll
        for (int o = 16; o > 0; o >>= 1) sq += __shfl_xor_sync(0xffffffffu, sq, o);
        float inv = rsqrtf(sq * (1.f / 128.f) + EPS_);

        int i0 = 2 * lane, i1 = 2 * lane + 64;
        float a0 = d0 * inv * g[i0]     + b[i0];
        float a1 = d1 * inv * g[i0 + 1] + b[i0 + 1];
        float a2 = d2 * inv * g[i1]     + b[i1];
        float a3 = d3 * inv * g[i1 + 1] + b[i1 + 1];

        const float kl = logf(1985.0f) / 63.0f;
        float f0 = 1.0f / ((float)lane        + expf((float)lane        * kl));
        float f1 = 1.0f / ((float)(lane + 32) + expf((float)(lane + 32) * kl));
        float c0, s0, c1, s1;
        sincosf((float)s * f0, &s0, &c0);
        sincosf((float)s * f1, &s1, &c1);

        float o0 = a0 * c0 - a1 * s0, o1 = a1 * c0 + a0 * s0;
        float o2 = a2 * c1 - a3 * s1, o3 = a3 * c1 + a2 * s1;

        unsigned h01, l01, h23, l23;
        split2pack(o0, o1, h01, l01);
        split2pack(o2, o3, h23, l23);
        *(unsigned*)&dh[dst + i0] = h01;
        *(unsigned*)&dl[dst + i0] = l01;
        *(unsigned*)&dh[dst + i1] = h23;
        *(unsigned*)&dl[dst + i1] = l23;
    } else {
        const float* p = qkv + (size_t)row * NQKV + 2560 + (slot - 20) * 96;
        size_t dst = ((size_t)row * HKV_ + (slot - 20)) * 96;
        float x0 = p[lane], x1 = p[lane + 32], x2 = p[lane + 64];
        float sum = x0 + x1 + x2;
        #pragma unroll
        for (int o = 16; o > 0; o >>= 1) sum += __shfl_xor_sync(0xffffffffu, sum, o);
        float mu = sum * (1.f / 96.f);
        float d0 = x0 - mu, d1 = x1 - mu, d2 = x2 - mu;
        float sq = d0 * d0 + d1 * d1 + d2 * d2;
        #pragma unroll
        for (int o = 16; o > 0; o >>= 1) sq += __shfl_xor_sync(0xffffffffu, sq, o);
        float inv = rsqrtf(sq * (1.f / 96.f) + EPS_);
        float y0 = d0 * inv * vn_g[lane]      + vn_b[lane];
        float y1 = d1 * inv * vn_g[lane + 32] + vn_b[lane + 32];
        float y2 = d2 * inv * vn_g[lane + 64] + vn_b[lane + 64];
        #pragma unroll
        for (int j = 0; j < 3; j++) {
            float v = (j == 0) ? y0 : (j == 1) ? y1 : y2;
            __nv_bfloat16 hi = __float2bfloat16(v);
            float lo = v - __bfloat162float(hi);
            g_vh[dst + lane + j * 32] = hi;
            g_vl[dst + lane + j * 32] = __float2bfloat16(lo);
        }
    }
}

// ==================== mma.sync attention ====================
#define Q_BYTES    32768
#define K_BYTES    16384
#define V_STRIDE   208
#define V_BYTES    (64 * V_STRIDE)
#define KV_BUF     (2 * K_BYTES + 2 * V_BYTES)
#define ATT_SMEM   (2 * Q_BYTES + 2 * KV_BUF)

__global__ __launch_bounds__(256, 1)
void attn_mma_kernel() {
    extern __shared__ __align__(1024) char sm[];
    const unsigned sb = smem_u32(sm);
    const int qb = blockIdx.x;
    const int h  = blockIdx.y;
    const int bb = blockIdx.z;
    const int hk = h & (HKV_ - 1);
    const int tid = threadIdx.x, wid = tid >> 5, lane = tid & 31;

    {   // Q loads (grouped with kv tile 0)
        const __nv_bfloat16* srcs[2];
        srcs[0] = g_qh; srcs[1] = g_ql;
        #pragma unroll
        for (int part = 0; part < 2; part++) {
            #pragma unroll
            for (int it = 0; it < 8; it++) {
                int chunk = it * 256 + tid;
                int row = chunk >> 4, c = chunk & 15;
                unsigned off = row * 256 + c * 16;
                off ^= (off >> 4) & 0x70;
                const __nv_bfloat16* src = srcs[part] +
                    ((size_t)(bb * S_ + qb * 128 + row) * HQ_ + h) * DQK_ + c * 8;
                CPASYNC16(sb + part * Q_BYTES + off, (const void*)src);
            }
        }
    }

    auto load_kv = [&](int kt, int buf) {
        unsigned base = sb + 2 * Q_BYTES + buf * KV_BUF;
        int s0 = kt * 64;
        const __nv_bfloat16* ksrc[2] = {g_kh, g_kl};
        #pragma unroll
        for (int part = 0; part < 2; part++) {
            #pragma unroll
            for (int it = 0; it < 4; it++) {
                int chunk = it * 256 + tid;
                int row = chunk >> 4, c = chunk & 15;
                unsigned off = row * 256 + c * 16;
                off ^= (off >> 4) & 0x70;
                const __nv_bfloat16* src = ksrc[part] +
                    ((size_t)(bb * S_ + s0 + row) * HKV_ + hk) * DQK_ + c * 8;
                CPASYNC16(base + part * K_BYTES + off, (const void*)src);
            }
        }
        const __nv_bfloat16* vsrc[2] = {g_vh, g_vl};
        #pragma unroll
        for (int part = 0; part < 2; part++) {
            #pragma unroll
            for (int it = 0; it < 3; it++) {
                int chunk = it * 256 + tid;
                int row = chunk / 12, c = chunk % 12;
                unsigned off = row * V_STRIDE + c * 16;
                const __nv_bfloat16* src = vsrc[part] +
                    ((size_t)(bb * S_ + s0 + row) * HKV_ + hk) * DV_ + c * 8;
                CPASYNC16(base + 2 * K_BYTES + part * V_BYTES + off, (const void*)src);
            }
        }
        CPASYNC_COMMIT();
    };

    load_kv(0, 0);    // group 0 = Q + kv0

    float o_[12][4];
    #pragma unroll
    for (int t = 0; t < 12; t++)
        #pragma unroll
        for (int q = 0; q < 4; q++) o_[t][q] = 0.f;
    float rs0 = 0.f, rs1 = 0.f;

    const float scale = 0.08838834764831845f;
    const int a_row  = wid * 16 + (lane & 15);
    const unsigned a_byte = (lane >> 4) << 4;
    const int b_rowc = (lane & 7) + ((lane >> 4) << 3);
    const unsigned b_byte = ((lane >> 3) & 1) << 4;

    const int NT = S_ / 64;
    for (int kb = 0; kb < NT; kb++) {
        int b = kb & 1;
        CPASYNC_WAIT0();
        __syncthreads();
        if (kb + 1 < NT) load_kv(kb + 1, b ^ 1);

        unsigned kvbase = sb + 2 * Q_BYTES + b * KV_BUF;
        unsigned baseKh = kvbase, baseKl = kvbase + K_BYTES;
        unsigned baseVh = kvbase + 2 * K_BYTES, baseVl = baseVh + V_BYTES;

        float sc[8][4];
        #pragma unroll
        for (int t = 0; t < 8; t++)
            #pragma unroll
            for (int q = 0; q < 4; q++) sc[t][q] = 0.f;

        #pragma unroll
        for (int ks = 0; ks < 8; ks++) {
            unsigned offA = (unsigned)a_row * 256 + a_byte + ks * 32;
            offA ^= (offA >> 4) & 0x70;
            unsigned qh0, qh1, qh2, qh3, ql0, ql1, ql2, ql3;
            LDSM4(qh0, qh1, qh2, qh3, sb + offA);
            LDSM4(ql0, ql1, ql2, ql3, sb + Q_BYTES + offA);
            #pragma unroll
            for (int p = 0; p < 4; p++) {
                unsigned offB = (unsigned)(p * 16 + b_rowc) * 256 + b_byte + ks * 32;
                offB ^= (offB >> 4) & 0x70;
                unsigned kh0, kh1, kh2, kh3, kl0, kl1, kl2, kl3;
                LDSM4(kh0, kh1, kh2, kh3, baseKh + offB);
                LDSM4(kl0, kl1, kl2, kl3, baseKl + offB);
                MMA16816(sc[2*p],   qh0, qh1, qh2, qh3, kh0, kh1);
                MMA16816(sc[2*p],   ql0, ql1, ql2, ql3, kh0, kh1);
                MMA16816(sc[2*p],   qh0, qh1, qh2, qh3, kl0, kl1);
                MMA16816(sc[2*p+1], qh0, qh1, qh2, qh3, kh2, kh3);
                MMA16816(sc[2*p+1], ql0, ql1, ql2, ql3, kh2, kh3);
                MMA16816(sc[2*p+1], qh0, qh1, qh2, qh3, kl2, kl3);
            }
        }

        #pragma unroll
        for (int t = 0; t < 8; t++) {
            #pragma unroll
            for (int q = 0; q < 4; q++) {
                float l = sc[t][q] * scale;
                float e = __expf(0.4f * l);
                float th = 1.f - __fdividef(2.f, e + 1.f);
                float pp = __expf(CLIP_ * th);
                sc[t][q] = pp;
                if (q < 2) rs0 += pp; else rs1 += pp;
            }
        }

        unsigned ah[4][4], al[4][4];
        #pragma unroll
        for (int j = 0; j < 4; j++) {
            split2pack(sc[2*j][0],   sc[2*j][1],   ah[j][0], al[j][0]);
            split2pack(sc[2*j][2],   sc[2*j][3],   ah[j][1], al[j][1]);
            split2pack(sc[2*j+1][0], sc[2*j+1][1], ah[j][2], al[j][2]);
            split2pack(sc[2*j+1][2], sc[2*j+1][3], ah[j][3], al[j][3]);
        }

        unsigned voff = (unsigned)(lane & 15) * V_STRIDE + ((lane >> 4) << 4);
        #pragma unroll
        for (int ct = 0; ct < 3; ct++) {
            #pragma unroll
            for (int half = 0; half < 2; half++) {
                #pragma unroll
                for (int j = 0; j < 4; j++) {
                    unsigned a0 = voff + j * (16 * V_STRIDE) + ct * 64 + half * 32;
                    unsigned vh0, vh1, vh2, vh3, vl0, vl1, vl2, vl3;
                    LDSM4T(vh0, vh1, vh2, vh3, baseVh + a0);
                    LDSM4T(vl0, vl1, vl2, vl3, baseVl + a0);
                    int nt = ct * 4 + half * 2;
                    MMA16816(o_[nt],   ah[j][0], ah[j][1], ah[j][2], ah[j][3], vh0, vh1);
                    MMA16816(o_[nt],   al[j][0], al[j][1], al[j][2], al[j][3], vh0, vh1);
                    MMA16816(o_[nt],   ah[j][0], ah[j][1], ah[j][2], ah[j][3], vl0, vl1);
                    MMA16816(o_[nt+1], ah[j][0], ah[j][1], ah[j][2], ah[j][3], vh2, vh3);
                    MMA16816(o_[nt+1], al[j][0], al[j][1], al[j][2], al[j][3], vh2, vh3);
                    MMA16816(o_[nt+1], ah[j][0], ah[j][1], ah[j][2], ah[j][3], vl2, vl3);
                }
            }
        }
    }

    rs0 += __shfl_xor_sync(0xffffffffu, rs0, 1);
    rs0 += __shfl_xor_sync(0xffffffffu, rs0, 2);
    rs1 += __shfl_xor_sync(0xffffffffu, rs1, 1);
    rs1 += __shfl_xor_sync(0xffffffffu, rs1, 2);
    float inv0 = 1.f / rs0, inv1 = 1.f / rs1;

    int r0 = qb * 128 + wid * 16 + (lane >> 2);
    size_t rowbase0 = ((size_t)(bb * S_ + r0)) * (HQ_ * DV_) + h * DV_;
    size_t rowbase1 = rowbase0 + 8 * (size_t)(HQ_ * DV_);
    #pragma unroll
    for (int nt = 0; nt < 12; nt++) {
        int c = nt * 8 + (lane & 3) * 2;
        unsigned h01, l01, h23, l23;
        split2pack(o_[nt][0] * inv0, o_[nt][1] * inv0, h01, l01);
        split2pack(o_[nt][2] * inv1, o_[nt][3] * inv1, h23, l23);
        *(unsigned*)&g_yh[rowbase0 + c] = h01;
        *(unsigned*)&g_yl[rowbase0 + c] = l01;
        *(unsigned*)&g_yh[rowbase1 + c] = h23;
        *(unsigned*)&g_yl[rowbase1 + c] = l23;
    }
}

// ---------------- launch ----------------
extern "C" void kernel_launch(void* const* d_in, const int* in_sizes, int n_in,
                              void* d_out, int out_size) {
    const float* x      = (const float*)d_in[0];
    const float* bn1_g  = (const float*)d_in[1];
    const float* bn1_ms = (const float*)d_in[2];
    const float* Wq     = (const float*)d_in[3];
    const float* Wk     = (const float*)d_in[4];
    const float* Wv     = (const float*)d_in[5];
    const float* qn_g   = (const float*)d_in[6];
    const float* qn_b   = (const float*)d_in[7];
    const float* kn_g   = (const float*)d_in[8];
    const float* kn_b   = (const float*)d_in[9];
    const float* vn_g   = (const float*)d_in[10];
    const float* vn_b   = (const float*)d_in[11];
    const float* Wo     = (const float*)d_in[12];
    const float* bo     = (const float*)d_in[13];
    const float* bn2_g  = (const float*)d_in[14];
    const float* bn2_ms = (const float*)d_in[15];
    float* out = (float*)d_out;

    float* pqkv;
    __nv_bfloat16 *phh, *phl, *pwth, *pwtl, *pwoh, *pwol, *pyh, *pyl;
    cudaGetSymbolAddress((void**)&pqkv, g_qkv);
    cudaGetSymbolAddress((void**)&phh, g_hh);
    cudaGetSymbolAddress((void**)&phl, g_hl);
    cudaGetSymbolAddress((void**)&pwth, g_wth);
    cudaGetSymbolAddress((void**)&pwtl, g_wtl);
    cudaGetSymbolAddress((void**)&pwoh, g_woh);
    cudaGetSymbolAddress((void**)&pwol, g_wol);
    cudaGetSymbolAddress((void**)&pyh, g_yh);
    cudaGetSymbolAddress((void**)&pyl, g_yl);

    cudaFuncSetAttribute(mma_gemm_kernel, cudaFuncAttributeMaxDynamicSharedMemorySize, GEMM_SMEM);
    cudaFuncSetAttribute(attn_mma_kernel, cudaFuncAttributeMaxDynamicSharedMemorySize, ATT_SMEM);

    // 1. rms_bn1 + split
    bn1split_kernel<<<(M_ * C_ / 4) / 256, 256>>>(x, bn1_g, bn1_ms, phh, phl);
    // 2. Wo transpose
    transpose_split_kernel<<<dim3(C_/32, C_/32), dim3(32,8)>>>(Wo, pwoh, pwol, C_, C_);
    // 3. packed QKV weight transpose
    transpose_qkv_kernel<<<dim3(NQKV/32, C_/32), dim3(32,8)>>>(Wq, Wk, Wv, pwth, pwtl);
    // 4. merged QKV projection (profiled launch)
    mma_gemm_kernel<<<dim3(NQKV/128, M_/128), 256, GEMM_SMEM>>>(phh, phl, pwth, pwtl, pqkv, M_, NQKV, C_, nullptr, nullptr, nullptr);
    // 5. merged LN (+RoPE)
    ln_all_kernel<<<(M_ * 24) / 8, 256>>>(pqkv, qn_g, qn_b, kn_g, kn_b, vn_g, vn_b);
    // 6. attention
    attn_mma_kernel<<<dim3(S_ / 128, HQ_, B_), 256, ATT_SMEM>>>();
    // 7. out projection + bias + rms_bn2 -> d_out
    mma_gemm_kernel<<<dim3(C_/128, M_/128), 256, GEMM_SMEM>>>(pyh, pyl, pwoh, pwol, out, M_, C_, HQ_*DV_, bo, bn2_g, bn2_ms);
}